// round 3
// baseline (speedup 1.0000x reference)
#include <cuda_runtime.h>

// ---------------- problem constants ----------------
#define NN   50000
#define EE   800000
#define CIN  128
#define HH   256
#define H4   1024
#define P_LD 768            // [p0 | A p0 | A^2 p0] concatenated per row
#define SLOPE 0.01f

// ---------------- scratch (device globals; no runtime allocation) ----------------
__device__ float  g_P [(size_t)NN * P_LD];   // 153.6 MB
__device__ float  g_h [(size_t)NN * HH];     // 51.2 MB
__device__ float  g_t [(size_t)NN * HH];     // 51.2 MB
__device__ float  g_zw[(size_t)NN * H4];     // 204.8 MB
__device__ int    g_deg[NN];
__device__ int    g_fill[NN];
__device__ int    g_rowptr[NN + 1];
__device__ int    g_csrc[EE];
__device__ float  g_cw[EE];
__device__ double g_stats[2 * H4];
__device__ float  g_coef[2 * H4];
__device__ int    g_is64;

// ---------------- utility ----------------
__global__ void zero_words(unsigned* p, int n) {
    int i = blockIdx.x * blockDim.x + threadIdx.x;
    if (i < n) p[i] = 0u;
}

// Detect whether edge_index is int64 (high 32-bit words all zero) or int32.
__global__ void detect_kernel(const unsigned* p) {
    __shared__ unsigned sh[256];
    unsigned o = 0;
    for (int i = threadIdx.x; i < 2048; i += 256) o |= p[2 * i + 1];
    sh[threadIdx.x] = o;
    __syncthreads();
    for (int s = 128; s > 0; s >>= 1) {
        if (threadIdx.x < s) sh[threadIdx.x] |= sh[threadIdx.x + s];
        __syncthreads();
    }
    if (threadIdx.x == 0) g_is64 = (sh[0] == 0u) ? 1 : 0;
}

__device__ __forceinline__ int eidx(const void* p, long i) {
    return g_is64 ? (int)((const long long*)p)[i] : ((const int*)p)[i];
}

// ---------------- CSR build ----------------
__global__ void hist_kernel(const void* ei) {
    int e = blockIdx.x * 256 + threadIdx.x;
    if (e < EE) atomicAdd(&g_deg[eidx(ei, (long)EE + e)], 1);
}

__global__ void exscan_kernel() {
    __shared__ int sh[1024];
    __shared__ int carry;
    int tid = threadIdx.x;
    if (tid == 0) carry = 0;
    __syncthreads();
    for (int base = 0; base < NN; base += 1024) {
        int v = (base + tid < NN) ? g_deg[base + tid] : 0;
        sh[tid] = v;
        __syncthreads();
        for (int off = 1; off < 1024; off <<= 1) {
            int t = (tid >= off) ? sh[tid - off] : 0;
            __syncthreads();
            sh[tid] += t;
            __syncthreads();
        }
        if (base + tid < NN) g_rowptr[base + tid] = carry + sh[tid] - v;
        int total = sh[1023];
        __syncthreads();
        if (tid == 0) carry += total;
        __syncthreads();
    }
    if (tid == 0) g_rowptr[NN] = carry;
}

__global__ void scatter_kernel(const void* ei, const float* __restrict__ ew) {
    int e = blockIdx.x * 256 + threadIdx.x;
    if (e < EE) {
        int d = eidx(ei, (long)EE + e);
        int pos = g_rowptr[d] + atomicAdd(&g_fill[d], 1);
        g_csrc[pos] = eidx(ei, e);
        g_cw[pos]   = ew[e];
    }
}

// ---------------- SpMM: out[row,:] = sum_e w_e * in[src_e,:]  (rows of P, ld=768) ----------------
__global__ void spmm_kernel(const float* __restrict__ in, float* __restrict__ out) {
    int row = blockIdx.x * 4 + threadIdx.y;       // NN divisible by 4
    int c   = threadIdx.x << 2;                   // 64 threads * float4 = 256 ch
    int beg = g_rowptr[row];
    int end = g_rowptr[row + 1];
    float4 acc = make_float4(0.f, 0.f, 0.f, 0.f);
    int e = beg;
    for (; e + 1 < end; e += 2) {
        int   s0 = g_csrc[e],   s1 = g_csrc[e + 1];
        float w0 = g_cw[e],     w1 = g_cw[e + 1];
        float4 v0 = *(const float4*)(in + (size_t)s0 * P_LD + c);
        float4 v1 = *(const float4*)(in + (size_t)s1 * P_LD + c);
        acc.x += w0 * v0.x + w1 * v1.x;
        acc.y += w0 * v0.y + w1 * v1.y;
        acc.z += w0 * v0.z + w1 * v1.z;
        acc.w += w0 * v0.w + w1 * v1.w;
    }
    if (e < end) {
        int s0 = g_csrc[e]; float w0 = g_cw[e];
        float4 v0 = *(const float4*)(in + (size_t)s0 * P_LD + c);
        acc.x += w0 * v0.x; acc.y += w0 * v0.y; acc.z += w0 * v0.z; acc.w += w0 * v0.w;
    }
    *(float4*)(out + (size_t)row * P_LD + c) = acc;
}

// ---------------- SGEMM: C[M,N] = (ACC? C:0) + A[M,K]@B[K,N] + bias ----------------
// 128x128 tile, 8x8 per thread, BK=8, 256 threads. Requires N%128==0, K%8==0.
template <bool ACC>
__global__ __launch_bounds__(256, 2)
void sgemm(const float* __restrict__ A, int lda,
           const float* __restrict__ B,
           const float* __restrict__ bias,
           float* __restrict__ C, int ldc,
           int M, int Nn, int Kk)
{
    __shared__ float As[8][128];
    __shared__ float Bs[8][128];
    const int tid  = threadIdx.x;
    const int bm   = blockIdx.y << 7;
    const int bn   = blockIdx.x << 7;
    const int arow = tid >> 1;
    const int ak   = (tid & 1) << 2;
    const int bk   = tid >> 5;
    const int bc   = (tid & 31) << 2;
    const int tx   = (tid & 15) << 3;
    const int ty   = (tid >> 4) << 3;

    float acc[8][8];
#pragma unroll
    for (int i = 0; i < 8; ++i)
#pragma unroll
        for (int j = 0; j < 8; ++j) acc[i][j] = 0.f;

    const bool aok = (bm + arow) < M;
    const float* Ap = A + (size_t)(bm + arow) * lda + ak;
    const float* Bp = B + (size_t)bk * Nn + bn + bc;

    for (int k0 = 0; k0 < Kk; k0 += 8) {
        float4 av = aok ? *(const float4*)(Ap + k0) : make_float4(0.f, 0.f, 0.f, 0.f);
        float4 bv = *(const float4*)(Bp + (size_t)k0 * Nn);
        As[ak + 0][arow] = av.x;
        As[ak + 1][arow] = av.y;
        As[ak + 2][arow] = av.z;
        As[ak + 3][arow] = av.w;
        *(float4*)&Bs[bk][bc] = bv;
        __syncthreads();
#pragma unroll
        for (int kk = 0; kk < 8; ++kk) {
            float a[8], b[8];
#pragma unroll
            for (int i = 0; i < 8; ++i) a[i] = As[kk][ty + i];
#pragma unroll
            for (int j = 0; j < 8; ++j) b[j] = Bs[kk][tx + j];
#pragma unroll
            for (int i = 0; i < 8; ++i)
#pragma unroll
                for (int j = 0; j < 8; ++j) acc[i][j] = fmaf(a[i], b[j], acc[i][j]);
        }
        __syncthreads();
    }

#pragma unroll
    for (int i = 0; i < 8; ++i) {
        int r = bm + ty + i;
        if (r < M) {
            float* Cp = C + (size_t)r * ldc + bn + tx;
#pragma unroll
            for (int j = 0; j < 8; j += 4) {
                float4 bsv = *(const float4*)(bias + bn + tx + j);
                float4 o;
                o.x = acc[i][j + 0] + bsv.x;
                o.y = acc[i][j + 1] + bsv.y;
                o.z = acc[i][j + 2] + bsv.z;
                o.w = acc[i][j + 3] + bsv.w;
                if (ACC) {
                    float4 c0 = *(const float4*)(Cp + j);
                    o.x += c0.x; o.y += c0.y; o.z += c0.z; o.w += c0.w;
                }
                *(float4*)(Cp + j) = o;
            }
        }
    }
}

// ---------------- BatchNorm: column stats (fp64 accum), coeffs, fused BN+LeakyReLU ----------------
__global__ void colstats_kernel(const float* __restrict__ X, int C, double* __restrict__ sums) {
    int tid  = threadIdx.x;
    int nloc = C >> 8;                       // 1 (C=256) or 4 (C=1024)
    double s[4] = {0, 0, 0, 0}, ss[4] = {0, 0, 0, 0};
    for (int r = blockIdx.x; r < NN; r += gridDim.x) {
        const float* row = X + (size_t)r * C;
        for (int i = 0; i < nloc; ++i) {
            float v = row[i * 256 + tid];
            s[i]  += (double)v;
            ss[i] += (double)v * (double)v;
        }
    }
    for (int i = 0; i < nloc; ++i) {
        atomicAdd(&sums[i * 256 + tid],       s[i]);
        atomicAdd(&sums[C + i * 256 + tid],  ss[i]);
    }
}

__global__ void bncoef_kernel(const double* __restrict__ sums,
                              const float* __restrict__ g, const float* __restrict__ b,
                              int C, float* __restrict__ coef) {
    int c = blockIdx.x * blockDim.x + threadIdx.x;
    if (c >= C) return;
    double m  = sums[c] * (1.0 / NN);
    double v  = sums[C + c] * (1.0 / NN) - m * m;
    double sc = (double)g[c] / sqrt(v + 1e-5);
    coef[c]     = (float)sc;
    coef[C + c] = (float)((double)b[c] - m * sc);
}

__global__ void bnact_kernel(const float* __restrict__ X, int ldx,
                             float* __restrict__ Y, int ldy,
                             int C, const float* __restrict__ coef) {
    for (int r = blockIdx.x; r < NN; r += gridDim.x) {
        const float* xr = X + (size_t)r * ldx;
        float*       yr = Y + (size_t)r * ldy;
        for (int c = threadIdx.x; c < C; c += blockDim.x) {
            float y = fmaf(xr[c], coef[c], coef[C + c]);
            yr[c] = (y > 0.f) ? y : SLOPE * y;
        }
    }
}

// ---------------- driver ----------------
extern "C" void kernel_launch(void* const* d_in, const int* in_sizes, int n_in,
                              void* d_out, int out_size) {
    const float* x       = (const float*)d_in[0];
    const void*  ei      = d_in[1];
    const float* ew      = (const float*)d_in[2];
    const float* W_emb   = (const float*)d_in[3];
    const float* b_emb   = (const float*)d_in[4];
    const float* conv0_W = (const float*)d_in[5];
    const float* conv0_b = (const float*)d_in[6];
    const float* norm_g  = (const float*)d_in[7];
    const float* norm_b  = (const float*)d_in[8];
    const float* conv_W  = (const float*)d_in[9];
    const float* conv_b  = (const float*)d_in[10];
    const float* mlp_W1  = (const float*)d_in[11];
    const float* mlp_b1  = (const float*)d_in[12];
    const float* mlp_g   = (const float*)d_in[13];
    const float* mlp_bb  = (const float*)d_in[14];
    const float* mlp_W2  = (const float*)d_in[15];
    const float* mlp_b2  = (const float*)d_in[16];
    const float* W_out   = (const float*)d_in[17];
    const float* b_out   = (const float*)d_in[18];
    float* out = (float*)d_out;

    float *P, *h, *t, *zw;
    int *deg, *fill;
    double* stats;
    float* coef;
    cudaGetSymbolAddress((void**)&P,    g_P);
    cudaGetSymbolAddress((void**)&h,    g_h);
    cudaGetSymbolAddress((void**)&t,    g_t);
    cudaGetSymbolAddress((void**)&zw,   g_zw);
    cudaGetSymbolAddress((void**)&deg,  g_deg);
    cudaGetSymbolAddress((void**)&fill, g_fill);
    cudaGetSymbolAddress((void**)&stats, g_stats);
    cudaGetSymbolAddress((void**)&coef,  g_coef);

    const int MT = (NN + 127) / 128;   // 391 M-tiles
    dim3 blk256(256);
    dim3 spmm_blk(64, 4);
    dim3 spmm_grd(NN / 4);

    // ---- CSR build (per launch; deterministic given inputs) ----
    zero_words<<<(NN + 255) / 256, blk256>>>((unsigned*)deg, NN);
    zero_words<<<(NN + 255) / 256, blk256>>>((unsigned*)fill, NN);
    detect_kernel<<<1, 256>>>((const unsigned*)ei);
    hist_kernel<<<EE / 256, blk256>>>(ei);
    exscan_kernel<<<1, 1024>>>();
    scatter_kernel<<<EE / 256, blk256>>>(ei, ew);

    // ---- embed: h0 = x@W_emb + b_emb -> P[:,0:256] ----
    sgemm<false><<<dim3(HH / 128, MT), blk256>>>(x, CIN, W_emb, b_emb, P, P_LD, NN, HH, CIN);
    // hops
    spmm_kernel<<<spmm_grd, spmm_blk>>>(P, P + HH);
    spmm_kernel<<<spmm_grd, spmm_blk>>>(P + HH, P + 2 * HH);
    // stacked TAGConv GEMM: h = P@[W0;W1;W2] + b
    sgemm<false><<<dim3(HH / 128, MT), blk256>>>(P, P_LD, conv0_W, conv0_b, h, HH, NN, HH, P_LD);

    for (int l = 0; l < 3; ++l) {
        // z1 = lrelu(BN(h)) -> P[:,0:256]
        zero_words<<<16, blk256>>>((unsigned*)stats, 4096);
        colstats_kernel<<<512, blk256>>>(h, HH, stats);
        bncoef_kernel<<<1, 256>>>(stats, norm_g + l * HH, norm_b + l * HH, HH, coef);
        bnact_kernel<<<2048, blk256>>>(h, HH, P, P_LD, HH, coef);
        // hops
        spmm_kernel<<<spmm_grd, spmm_blk>>>(P, P + HH);
        spmm_kernel<<<spmm_grd, spmm_blk>>>(P + HH, P + 2 * HH);
        // t = P @ convW_l + conv_b_l
        sgemm<false><<<dim3(HH / 128, MT), blk256>>>(P, P_LD, conv_W + (size_t)l * 3 * HH * HH,
                                                     conv_b + l * HH, t, HH, NN, HH, P_LD);
        // zw = t @ W1 + b1
        sgemm<false><<<dim3(H4 / 128, MT), blk256>>>(t, HH, mlp_W1 + (size_t)l * HH * H4,
                                                     mlp_b1 + l * H4, zw, H4, NN, H4, HH);
        // zw = lrelu(BN(zw)) in place
        zero_words<<<16, blk256>>>((unsigned*)stats, 4096);
        colstats_kernel<<<512, blk256>>>(zw, H4, stats);
        bncoef_kernel<<<4, 256>>>(stats, mlp_g + l * H4, mlp_bb + l * H4, H4, coef);
        bnact_kernel<<<2048, blk256>>>(zw, H4, zw, H4, H4, coef);
        // h += zw @ W2 + b2   (residual)
        sgemm<true><<<dim3(HH / 128, MT), blk256>>>(zw, H4, mlp_W2 + (size_t)l * H4 * HH,
                                                    mlp_b2 + l * HH, h, HH, NN, HH, H4);
    }

    // out = h @ W_out + b_out
    sgemm<false><<<dim3(CIN / 128, MT), blk256>>>(h, HH, W_out, b_out, out, CIN, NN, CIN, HH);
}

// round 8
// speedup vs baseline: 1.3136x; 1.3136x over previous
#include <cuda_runtime.h>
#include <cstdint>

// ---------------- problem constants ----------------
#define NN   50000
#define EE   800000
#define CIN  128
#define HH   256
#define H4   1024
#define P_LD 768            // [p0 | A p0 | A^2 p0] concatenated per row
#define SLOPE 0.01f

// ---------------- scratch (device globals; no runtime allocation) ----------------
__device__ float  g_P [(size_t)NN * P_LD];
__device__ float  g_h [(size_t)NN * HH];
__device__ float  g_t [(size_t)NN * HH];
__device__ float  g_zw[(size_t)NN * H4];
__device__ float  g_Bt[2424832];             // all transposed weights, [N,K] row-major
__device__ int    g_deg[NN];
__device__ int    g_fill[NN];
__device__ int    g_rowptr[NN + 1];
__device__ int    g_csrc[EE];
__device__ float  g_cw[EE];
__device__ double g_stats[2 * H4];
__device__ float  g_coef[2 * H4];
__device__ int    g_is64;

// transposed-weight offsets inside g_Bt
#define OFF_EMB  0          // 256x128
#define OFF_C0   32768      // 256x768
#define OFF_CV   229376     // 3 x 256x768
#define OFF_W1   819200     // 3 x 1024x256
#define OFF_W2   1605632    // 3 x 256x1024
#define OFF_OUT  2392064    // 128x256

// ---------------- helpers ----------------
__device__ __forceinline__ uint32_t smem_u32(const void* p) {
    uint32_t a;
    asm("{ .reg .u64 t; cvta.to.shared.u64 t, %1; cvt.u32.u64 %0, t; }" : "=r"(a) : "l"(p));
    return a;
}
__device__ __forceinline__ uint32_t f2tf(float f) {
    uint32_t r;
    asm("cvt.rna.tf32.f32 %0, %1;" : "=r"(r) : "f"(f));
    return r;
}
// split x into tf32 hi + tf32 lo (lo = tf32(x - float(hi)))
__device__ __forceinline__ void tfsplit(float x, uint32_t& hi, uint32_t& lo) {
    hi = f2tf(x);
    lo = f2tf(x - __uint_as_float(hi));
}

// ---------------- utility ----------------
__global__ void zero_words(unsigned* p, int n) {
    int i = blockIdx.x * blockDim.x + threadIdx.x;
    if (i < n) p[i] = 0u;
}

__global__ void detect_kernel(const unsigned* p) {
    __shared__ unsigned sh[256];
    unsigned o = 0;
    for (int i = threadIdx.x; i < 2048; i += 256) o |= p[2 * i + 1];
    sh[threadIdx.x] = o;
    __syncthreads();
    for (int s = 128; s > 0; s >>= 1) {
        if (threadIdx.x < s) sh[threadIdx.x] |= sh[threadIdx.x + s];
        __syncthreads();
    }
    if (threadIdx.x == 0) g_is64 = (sh[0] == 0u) ? 1 : 0;
}

__device__ __forceinline__ int eidx(const void* p, long i) {
    return g_is64 ? (int)((const long long*)p)[i] : ((const int*)p)[i];
}

// ---------------- CSR build ----------------
__global__ void hist_kernel(const void* ei) {
    int e = blockIdx.x * 256 + threadIdx.x;
    if (e < EE) atomicAdd(&g_deg[eidx(ei, (long)EE + e)], 1);
}

__global__ void exscan_kernel() {
    __shared__ int sh[1024];
    __shared__ int carry;
    int tid = threadIdx.x;
    if (tid == 0) carry = 0;
    __syncthreads();
    for (int base = 0; base < NN; base += 1024) {
        int v = (base + tid < NN) ? g_deg[base + tid] : 0;
        sh[tid] = v;
        __syncthreads();
        for (int off = 1; off < 1024; off <<= 1) {
            int t = (tid >= off) ? sh[tid - off] : 0;
            __syncthreads();
            sh[tid] += t;
            __syncthreads();
        }
        if (base + tid < NN) g_rowptr[base + tid] = carry + sh[tid] - v;
        int total = sh[1023];
        __syncthreads();
        if (tid == 0) carry += total;
        __syncthreads();
    }
    if (tid == 0) g_rowptr[NN] = carry;
}

__global__ void scatter_kernel(const void* ei, const float* __restrict__ ew) {
    int e = blockIdx.x * 256 + threadIdx.x;
    if (e < EE) {
        int d = eidx(ei, (long)EE + e);
        int pos = g_rowptr[d] + atomicAdd(&g_fill[d], 1);
        g_csrc[pos] = eidx(ei, e);
        g_cw[pos]   = ew[e];
    }
}

// ---------------- SpMM ----------------
__global__ void spmm_kernel(const float* __restrict__ in, float* __restrict__ out) {
    int row = blockIdx.x * 4 + threadIdx.y;
    int c   = threadIdx.x << 2;
    int beg = g_rowptr[row];
    int end = g_rowptr[row + 1];
    float4 acc = make_float4(0.f, 0.f, 0.f, 0.f);
    int e = beg;
    for (; e + 1 < end; e += 2) {
        int   s0 = g_csrc[e],   s1 = g_csrc[e + 1];
        float w0 = g_cw[e],     w1 = g_cw[e + 1];
        float4 v0 = *(const float4*)(in + (size_t)s0 * P_LD + c);
        float4 v1 = *(const float4*)(in + (size_t)s1 * P_LD + c);
        acc.x += w0 * v0.x + w1 * v1.x;
        acc.y += w0 * v0.y + w1 * v1.y;
        acc.z += w0 * v0.z + w1 * v1.z;
        acc.w += w0 * v0.w + w1 * v1.w;
    }
    if (e < end) {
        int s0 = g_csrc[e]; float w0 = g_cw[e];
        float4 v0 = *(const float4*)(in + (size_t)s0 * P_LD + c);
        acc.x += w0 * v0.x; acc.y += w0 * v0.y; acc.z += w0 * v0.z; acc.w += w0 * v0.w;
    }
    *(float4*)(out + (size_t)row * P_LD + c) = acc;
}

// ---------------- weight transpose: in[K,N] -> out[N,K] ----------------
__global__ void transpose_kernel(const float* __restrict__ in, float* __restrict__ out,
                                 int K, int N) {
    __shared__ float t[32][33];
    int n0 = blockIdx.x << 5, k0 = blockIdx.y << 5;
    int tx = threadIdx.x, ty = threadIdx.y;
#pragma unroll
    for (int r = 0; r < 32; r += 8)
        t[ty + r][tx] = in[(size_t)(k0 + ty + r) * N + n0 + tx];
    __syncthreads();
#pragma unroll
    for (int r = 0; r < 32; r += 8)
        out[(size_t)(n0 + ty + r) * K + k0 + tx] = t[tx][ty + r];
}

// ---------------- mma.sync tf32x3 GEMM ----------------
// C[M,N] = (ACC? C:0) + A[M,K] @ Bt[N,K]^T + bias  with fp32-accuracy via
// 3-term tf32 error compensation: hi*hi + lo*hi + hi*lo.
// CTA tile 128x128, BK=32, double-buffered cp.async, 8 warps of 64x32 warp tiles.
#define TSTRIDE   36
#define TILE_FL   (128 * TSTRIDE)          // floats per tile buffer
#define TILE_BY   (TILE_FL * 4)            // 18432 B
#define GSM_TOTAL (4 * TILE_BY)            // 73728 B

#define MMA_T(d, a0, a1, a2, a3, b0, b1) \
    asm volatile("mma.sync.aligned.m16n8k8.row.col.f32.tf32.tf32.f32 " \
        "{%0,%1,%2,%3}, {%4,%5,%6,%7}, {%8,%9}, {%0,%1,%2,%3};" \
        : "+f"((d)[0]), "+f"((d)[1]), "+f"((d)[2]), "+f"((d)[3]) \
        : "r"(a0), "r"(a1), "r"(a2), "r"(a3), "r"(b0), "r"(b1))

__global__ __launch_bounds__(256, 1)
void mma_gemm_tf32(const float* __restrict__ A, int lda,
                   const float* __restrict__ Bt,      // [N,K] row-major
                   const float* __restrict__ bias,
                   float* __restrict__ C, int ldc,
                   int M, int K, int ACC)
{
    extern __shared__ __align__(16) float smem[];
    const uint32_t sb = smem_u32(smem);
    float (*As)[128][TSTRIDE] = (float(*)[128][TSTRIDE])(smem);
    float (*Bs)[128][TSTRIDE] = (float(*)[128][TSTRIDE])(smem + 2 * TILE_FL);

    const int tid  = threadIdx.x;
    const int lane = tid & 31;
    const int wid  = tid >> 5;
    const int bm   = blockIdx.y << 7;
    const int bn   = blockIdx.x << 7;
    const int wm   = (wid & 1) << 6;     // 0 or 64
    const int wn   = (wid >> 1) << 5;    // 0,32,64,96
    const int g    = lane >> 2;          // group id 0..7
    const int tg   = lane & 3;           // thread-in-group 0..3

    float acc[4][4][4];
#pragma unroll
    for (int mi = 0; mi < 4; ++mi)
#pragma unroll
        for (int ni = 0; ni < 4; ++ni)
#pragma unroll
            for (int q = 0; q < 4; ++q) acc[mi][ni][q] = 0.f;

    const int nc = K >> 5;

    auto prefetch = [&](int i) {
        const int s  = i & 1;
        const int kc = i << 5;
        const uint32_t dA = sb + (uint32_t)s * TILE_BY;
        const uint32_t dB = sb + 2u * TILE_BY + (uint32_t)s * TILE_BY;
#pragma unroll
        for (int r = 0; r < 4; ++r) {
            int id  = tid + (r << 8);          // 0..1023
            int row = id >> 3, c4 = id & 7;    // 128 rows x 8 x 16B
            uint32_t off = (uint32_t)(row * (TSTRIDE * 4) + (c4 << 4));
            const float* srcA = A + (size_t)(bm + row) * lda + kc + (c4 << 2);
            int sz = (bm + row < M) ? 16 : 0;
            asm volatile("cp.async.ca.shared.global [%0], [%1], 16, %2;"
                         :: "r"(dA + off), "l"(srcA), "r"(sz));
            const float* srcB = Bt + (size_t)(bn + row) * K + kc + (c4 << 2);
            asm volatile("cp.async.ca.shared.global [%0], [%1], 16;"
                         :: "r"(dB + off), "l"(srcB));
        }
        asm volatile("cp.async.commit_group;" ::: "memory");
    };

    prefetch(0);
    for (int i = 0; i < nc; ++i) {
        if (i + 1 < nc) {
            prefetch(i + 1);
            asm volatile("cp.async.wait_group 1;" ::: "memory");
        } else {
            asm volatile("cp.async.wait_group 0;" ::: "memory");
        }
        __syncthreads();

        const int s = i & 1;
#pragma unroll
        for (int k8 = 0; k8 < 4; ++k8) {
            const int kk = (k8 << 3) + tg;
            // B fragments (hi + lo), shared across the mi loop
            uint32_t bh[4][2], bl[4][2];
#pragma unroll
            for (int ni = 0; ni < 4; ++ni) {
                int c = wn + (ni << 3) + g;
                tfsplit(Bs[s][c][kk],     bh[ni][0], bl[ni][0]);
                tfsplit(Bs[s][c][kk + 4], bh[ni][1], bl[ni][1]);
            }
#pragma unroll
            for (int mi = 0; mi < 4; ++mi) {
                int r = wm + (mi << 4) + g;
                uint32_t ah[4], al[4];
                tfsplit(As[s][r][kk],          ah[0], al[0]);
                tfsplit(As[s][r + 8][kk],      ah[1], al[1]);
                tfsplit(As[s][r][kk + 4],      ah[2], al[2]);
                tfsplit(As[s][r + 8][kk + 4],  ah[3], al[3]);
#pragma unroll
                for (int ni = 0; ni < 4; ++ni) {
                    MMA_T(acc[mi][ni], al[0], al[1], al[2], al[3], bh[ni][0], bh[ni][1]);
                    MMA_T(acc[mi][ni], ah[0], ah[1], ah[2], ah[3], bl[ni][0], bl[ni][1]);
                    MMA_T(acc[mi][ni], ah[0], ah[1], ah[2], ah[3], bh[ni][0], bh[ni][1]);
                }
            }
        }
        __syncthreads();
    }

    // ---- epilogue: bias add (+ optional accumulate into C) ----
#pragma unroll
    for (int mi = 0; mi < 4; ++mi) {
        int r0 = bm + wm + (mi << 4) + g;
#pragma unroll
        for (int ni = 0; ni < 4; ++ni) {
            int c0 = bn + wn + (ni << 3) + (tg << 1);
            float2 bv = *(const float2*)(bias + c0);
            if (r0 < M) {
                float* p = C + (size_t)r0 * ldc + c0;
                float2 o = make_float2(acc[mi][ni][0] + bv.x, acc[mi][ni][1] + bv.y);
                if (ACC) { float2 c = *(const float2*)p; o.x += c.x; o.y += c.y; }
                *(float2*)p = o;
            }
            if (r0 + 8 < M) {
                float* p = C + (size_t)(r0 + 8) * ldc + c0;
                float2 o = make_float2(acc[mi][ni][2] + bv.x, acc[mi][ni][3] + bv.y);
                if (ACC) { float2 c = *(const float2*)p; o.x += c.x; o.y += c.y; }
                *(float2*)p = o;
            }
        }
    }
}

// ---------------- BatchNorm ----------------
__global__ void colstats_kernel(const float* __restrict__ X, int C, double* __restrict__ sums) {
    int tid  = threadIdx.x;
    int nloc = C >> 8;
    double s[4] = {0, 0, 0, 0}, ss[4] = {0, 0, 0, 0};
    for (int r = blockIdx.x; r < NN; r += gridDim.x) {
        const float* row = X + (size_t)r * C;
        for (int i = 0; i < nloc; ++i) {
            float v = row[i * 256 + tid];
            s[i]  += (double)v;
            ss[i] += (double)v * (double)v;
        }
    }
    for (int i = 0; i < nloc; ++i) {
        atomicAdd(&sums[i * 256 + tid],      s[i]);
        atomicAdd(&sums[C + i * 256 + tid], ss[i]);
    }
}

__global__ void bncoef_kernel(const double* __restrict__ sums,
                              const float* __restrict__ g, const float* __restrict__ b,
                              int C, float* __restrict__ coef) {
    int c = blockIdx.x * blockDim.x + threadIdx.x;
    if (c >= C) return;
    double m  = sums[c] * (1.0 / NN);
    double v  = sums[C + c] * (1.0 / NN) - m * m;
    double sc = (double)g[c] / sqrt(v + 1e-5);
    coef[c]     = (float)sc;
    coef[C + c] = (float)((double)b[c] - m * sc);
}

__global__ void bnact_kernel(const float* __restrict__ X, int ldx,
                             float* __restrict__ Y, int ldy,
                             int C, const float* __restrict__ coef) {
    for (int r = blockIdx.x; r < NN; r += gridDim.x) {
        const float* xr = X + (size_t)r * ldx;
        float*       yr = Y + (size_t)r * ldy;
        for (int c = threadIdx.x; c < C; c += blockDim.x) {
            float y = fmaf(xr[c], coef[c], coef[C + c]);
            yr[c] = (y > 0.f) ? y : SLOPE * y;
        }
    }
}

// ---------------- driver ----------------
extern "C" void kernel_launch(void* const* d_in, const int* in_sizes, int n_in,
                              void* d_out, int out_size) {
    const float* x       = (const float*)d_in[0];
    const void*  ei      = d_in[1];
    const float* ew      = (const float*)d_in[2];
    const float* W_emb   = (const float*)d_in[3];
    const float* b_emb   = (const float*)d_in[4];
    const float* conv0_W = (const float*)d_in[5];
    const float* conv0_b = (const float*)d_in[6];
    const float* norm_g  = (const float*)d_in[7];
    const float* norm_b  = (const float*)d_in[8];
    const float* conv_W  = (const float*)d_in[9];
    const float* conv_b  = (const float*)d_in[10];
    const float* mlp_W1  = (const float*)d_in[11];
    const float* mlp_b1  = (const float*)d_in[12];
    const float* mlp_g   = (const float*)d_in[13];
    const float* mlp_bb  = (const float*)d_in[14];
    const float* mlp_W2  = (const float*)d_in[15];
    const float* mlp_b2  = (const float*)d_in[16];
    const float* W_out   = (const float*)d_in[17];
    const float* b_out   = (const float*)d_in[18];
    float* out = (float*)d_out;

    float *P, *h, *t, *zw, *Bt;
    int *deg, *fill;
    double* stats;
    float* coef;
    cudaGetSymbolAddress((void**)&P,     g_P);
    cudaGetSymbolAddress((void**)&h,     g_h);
    cudaGetSymbolAddress((void**)&t,     g_t);
    cudaGetSymbolAddress((void**)&zw,    g_zw);
    cudaGetSymbolAddress((void**)&Bt,    g_Bt);
    cudaGetSymbolAddress((void**)&deg,   g_deg);
    cudaGetSymbolAddress((void**)&fill,  g_fill);
    cudaGetSymbolAddress((void**)&stats, g_stats);
    cudaGetSymbolAddress((void**)&coef,  g_coef);

    cudaFuncSetAttribute(mma_gemm_tf32, cudaFuncAttributeMaxDynamicSharedMemorySize, GSM_TOTAL);

    const int MT = (NN + 127) / 128;   // 391 M-tiles
    dim3 blk256(256);
    dim3 spmm_blk(64, 4);
    dim3 spmm_grd(NN / 4);
    dim3 tb(32, 8);

    // ---- CSR build ----
    zero_words<<<(NN + 255) / 256, blk256>>>((unsigned*)deg, NN);
    zero_words<<<(NN + 255) / 256, blk256>>>((unsigned*)fill, NN);
    detect_kernel<<<1, 256>>>((const unsigned*)ei);
    hist_kernel<<<EE / 256, blk256>>>(ei);
    exscan_kernel<<<1, 1024>>>();
    scatter_kernel<<<EE / 256, blk256>>>(ei, ew);

    // ---- weight transposes into [N,K] ----
    transpose_kernel<<<dim3(HH / 32, CIN / 32), tb>>>(W_emb, Bt + OFF_EMB, CIN, HH);
    transpose_kernel<<<dim3(HH / 32, P_LD / 32), tb>>>(conv0_W, Bt + OFF_C0, P_LD, HH);
    for (int l = 0; l < 3; ++l) {
        transpose_kernel<<<dim3(HH / 32, P_LD / 32), tb>>>(
            conv_W + (size_t)l * P_LD * HH, Bt + OFF_CV + (size_t)l * P_LD * HH, P_LD, HH);
        transpose_kernel<<<dim3(H4 / 32, HH / 32), tb>>>(
            mlp_W1 + (size_t)l * HH * H4, Bt + OFF_W1 + (size_t)l * HH * H4, HH, H4);
        transpose_kernel<<<dim3(HH / 32, H4 / 32), tb>>>(
            mlp_W2 + (size_t)l * H4 * HH, Bt + OFF_W2 + (size_t)l * H4 * HH, H4, HH);
    }
    transpose_kernel<<<dim3(CIN / 32, HH / 32), tb>>>(W_out, Bt + OFF_OUT, HH, CIN);

    // ---- embed: h0 = x@W_emb + b_emb -> P[:,0:256] ----
    mma_gemm_tf32<<<dim3(HH / 128, MT), blk256, GSM_TOTAL>>>(
        x, CIN, Bt + OFF_EMB, b_emb, P, P_LD, NN, CIN, 0);
    spmm_kernel<<<spmm_grd, spmm_blk>>>(P, P + HH);
    spmm_kernel<<<spmm_grd, spmm_blk>>>(P + HH, P + 2 * HH);
    mma_gemm_tf32<<<dim3(HH / 128, MT), blk256, GSM_TOTAL>>>(
        P, P_LD, Bt + OFF_C0, conv0_b, h, HH, NN, P_LD, 0);

    for (int l = 0; l < 3; ++l) {
        zero_words<<<16, blk256>>>((unsigned*)stats, 4096);
        colstats_kernel<<<512, blk256>>>(h, HH, stats);
        bncoef_kernel<<<1, 256>>>(stats, norm_g + l * HH, norm_b + l * HH, HH, coef);
        bnact_kernel<<<2048, blk256>>>(h, HH, P, P_LD, HH, coef);
        spmm_kernel<<<spmm_grd, spmm_blk>>>(P, P + HH);
        spmm_kernel<<<spmm_grd, spmm_blk>>>(P + HH, P + 2 * HH);
        mma_gemm_tf32<<<dim3(HH / 128, MT), blk256, GSM_TOTAL>>>(
            P, P_LD, Bt + OFF_CV + (size_t)l * P_LD * HH, conv_b + l * HH, t, HH, NN, P_LD, 0);
        mma_gemm_tf32<<<dim3(H4 / 128, MT), blk256, GSM_TOTAL>>>(
            t, HH, Bt + OFF_W1 + (size_t)l * HH * H4, mlp_b1 + l * H4, zw, H4, NN, HH, 0);
        zero_words<<<16, blk256>>>((unsigned*)stats, 4096);
        colstats_kernel<<<512, blk256>>>(zw, H4, stats);
        bncoef_kernel<<<4, 256>>>(stats, mlp_g + l * H4, mlp_bb + l * H4, H4, coef);
        bnact_kernel<<<2048, blk256>>>(zw, H4, zw, H4, H4, coef);
        mma_gemm_tf32<<<dim3(HH / 128, MT), blk256, GSM_TOTAL>>>(
            zw, H4, Bt + OFF_W2 + (size_t)l * H4 * HH, mlp_b2 + l * HH, h, HH, NN, H4, 1);
    }

    mma_gemm_tf32<<<dim3(CIN / 128, MT), blk256, GSM_TOTAL>>>(
        h, HH, Bt + OFF_OUT, b_out, out, CIN, NN, HH, 0);
}

// round 10
// speedup vs baseline: 1.6026x; 1.2200x over previous
#include <cuda_runtime.h>
#include <cuda_bf16.h>
#include <cstdint>

// ---------------- problem constants ----------------
#define NN   50000
#define EE   800000
#define CIN  128
#define HH   256
#define H4   1024
#define P_LD 768            // [p0 | A p0 | A^2 p0] concatenated per row
#define SLOPE 0.01f

// ---------------- scratch (device globals; no runtime allocation) ----------------
__device__ float  g_P [(size_t)NN * P_LD];
__device__ float  g_h [(size_t)NN * HH];
__device__ float  g_t [(size_t)NN * HH];
__device__ float  g_zw[(size_t)NN * H4];
__device__ float  g_Bt[2424832];             // all transposed weights, [N,K] row-major
__device__ int    g_deg[NN];
__device__ int    g_fill[NN];
__device__ int    g_rowptr[NN + 1];
__device__ int    g_csrc[EE];
__device__ float  g_cw[EE];
__device__ double g_stats[2 * H4];
__device__ float  g_coef[2 * H4];
__device__ int    g_is64;

// transposed-weight offsets inside g_Bt
#define OFF_EMB  0          // 256x128
#define OFF_C0   32768      // 256x768
#define OFF_CV   229376     // 3 x 256x768
#define OFF_W1   819200     // 3 x 1024x256
#define OFF_W2   1605632    // 3 x 256x1024
#define OFF_OUT  2392064    // 128x256

// ---------------- helpers ----------------
__device__ __forceinline__ uint32_t smem_u32(const void* p) {
    uint32_t a;
    asm("{ .reg .u64 t; cvta.to.shared.u64 t, %1; cvt.u32.u64 %0, t; }" : "=r"(a) : "l"(p));
    return a;
}

// ---------------- utility ----------------
__global__ void zero_words(unsigned* p, int n) {
    int i = blockIdx.x * blockDim.x + threadIdx.x;
    if (i < n) p[i] = 0u;
}

__global__ void detect_kernel(const unsigned* p) {
    __shared__ unsigned sh[256];
    unsigned o = 0;
    for (int i = threadIdx.x; i < 2048; i += 256) o |= p[2 * i + 1];
    sh[threadIdx.x] = o;
    __syncthreads();
    for (int s = 128; s > 0; s >>= 1) {
        if (threadIdx.x < s) sh[threadIdx.x] |= sh[threadIdx.x + s];
        __syncthreads();
    }
    if (threadIdx.x == 0) g_is64 = (sh[0] == 0u) ? 1 : 0;
}

__device__ __forceinline__ int eidx(const void* p, long i) {
    return g_is64 ? (int)((const long long*)p)[i] : ((const int*)p)[i];
}

// ---------------- CSR build ----------------
__global__ void hist_kernel(const void* ei) {
    int e = blockIdx.x * 256 + threadIdx.x;
    if (e < EE) atomicAdd(&g_deg[eidx(ei, (long)EE + e)], 1);
}

__global__ void exscan_kernel() {
    __shared__ int sh[1024];
    __shared__ int carry;
    int tid = threadIdx.x;
    if (tid == 0) carry = 0;
    __syncthreads();
    for (int base = 0; base < NN; base += 1024) {
        int v = (base + tid < NN) ? g_deg[base + tid] : 0;
        sh[tid] = v;
        __syncthreads();
        for (int off = 1; off < 1024; off <<= 1) {
            int t = (tid >= off) ? sh[tid - off] : 0;
            __syncthreads();
            sh[tid] += t;
            __syncthreads();
        }
        if (base + tid < NN) g_rowptr[base + tid] = carry + sh[tid] - v;
        int total = sh[1023];
        __syncthreads();
        if (tid == 0) carry += total;
        __syncthreads();
    }
    if (tid == 0) g_rowptr[NN] = carry;
}

__global__ void scatter_kernel(const void* ei, const float* __restrict__ ew) {
    int e = blockIdx.x * 256 + threadIdx.x;
    if (e < EE) {
        int d = eidx(ei, (long)EE + e);
        int pos = g_rowptr[d] + atomicAdd(&g_fill[d], 1);
        g_csrc[pos] = eidx(ei, e);
        g_cw[pos]   = ew[e];
    }
}

// ---------------- SpMM ----------------
__global__ void spmm_kernel(const float* __restrict__ in, float* __restrict__ out) {
    int row = blockIdx.x * 4 + threadIdx.y;
    int c   = threadIdx.x << 2;
    int beg = g_rowptr[row];
    int end = g_rowptr[row + 1];
    float4 acc = make_float4(0.f, 0.f, 0.f, 0.f);
    int e = beg;
    for (; e + 1 < end; e += 2) {
        int   s0 = g_csrc[e],   s1 = g_csrc[e + 1];
        float w0 = g_cw[e],     w1 = g_cw[e + 1];
        float4 v0 = *(const float4*)(in + (size_t)s0 * P_LD + c);
        float4 v1 = *(const float4*)(in + (size_t)s1 * P_LD + c);
        acc.x += w0 * v0.x + w1 * v1.x;
        acc.y += w0 * v0.y + w1 * v1.y;
        acc.z += w0 * v0.z + w1 * v1.z;
        acc.w += w0 * v0.w + w1 * v1.w;
    }
    if (e < end) {
        int s0 = g_csrc[e]; float w0 = g_cw[e];
        float4 v0 = *(const float4*)(in + (size_t)s0 * P_LD + c);
        acc.x += w0 * v0.x; acc.y += w0 * v0.y; acc.z += w0 * v0.z; acc.w += w0 * v0.w;
    }
    *(float4*)(out + (size_t)row * P_LD + c) = acc;
}

// ---------------- weight transpose: in[K,N] -> out[N,K] ----------------
__global__ void transpose_kernel(const float* __restrict__ in, float* __restrict__ out,
                                 int K, int N) {
    __shared__ float t[32][33];
    int n0 = blockIdx.x << 5, k0 = blockIdx.y << 5;
    int tx = threadIdx.x, ty = threadIdx.y;
#pragma unroll
    for (int r = 0; r < 32; r += 8)
        t[ty + r][tx] = in[(size_t)(k0 + ty + r) * N + n0 + tx];
    __syncthreads();
#pragma unroll
    for (int r = 0; r < 32; r += 8)
        out[(size_t)(n0 + ty + r) * K + k0 + tx] = t[tx][ty + r];
}

// ---------------- mma.sync bf16x3 GEMM ----------------
// C[M,N] = (ACC? C:0) + A[M,K] @ Bt[N,K]^T + bias  with near-fp32 accuracy via
// bf16 error compensation: hi*hi + lo*hi + hi*lo (lo = bf16(x - bf16(x))).
// CTA tile 128x128, BK=32, register-staged double-buffered SMEM (bf16 hi/lo
// tiles, 80B row stride -> ldmatrix conflict-free), 8 warps of 64x32 tiles.
#define ROWB    80                     // bytes per 32-col bf16 row (pad 32->40)
#define TILE_B  (128 * ROWB)           // 10240 B per tile
#define AH_OFF  0
#define AL_OFF  TILE_B
#define BH_OFF  (2 * TILE_B)
#define BL_OFF  (3 * TILE_B)
#define STG_BY  (4 * TILE_B)           // 40960 B per stage
#define GSM_TOTAL (2 * STG_BY)         // 81920 B

#define MMA_B(d, a, b0, b1) \
    asm volatile("mma.sync.aligned.m16n8k16.row.col.f32.bf16.bf16.f32 " \
        "{%0,%1,%2,%3}, {%4,%5,%6,%7}, {%8,%9}, {%0,%1,%2,%3};" \
        : "+f"((d)[0]), "+f"((d)[1]), "+f"((d)[2]), "+f"((d)[3]) \
        : "r"((a)[0]), "r"((a)[1]), "r"((a)[2]), "r"((a)[3]), "r"(b0), "r"(b1))

#define LDM_X4(r, addr) \
    asm volatile("ldmatrix.sync.aligned.m8n8.x4.shared.b16 {%0,%1,%2,%3}, [%4];" \
        : "=r"((r)[0]), "=r"((r)[1]), "=r"((r)[2]), "=r"((r)[3]) : "r"(addr))

#define LDM_X2(r0, r1, addr) \
    asm volatile("ldmatrix.sync.aligned.m8n8.x2.shared.b16 {%0,%1}, [%2];" \
        : "=r"(r0), "=r"(r1) : "r"(addr))

// convert (x,y) -> packed bf16x2 hi word + lo word
__device__ __forceinline__ void cvt2(float x, float y, uint32_t& hw, uint32_t& lw) {
    __nv_bfloat16 hx = __float2bfloat16(x), hy = __float2bfloat16(y);
    __nv_bfloat16 lx = __float2bfloat16(x - __bfloat162float(hx));
    __nv_bfloat16 ly = __float2bfloat16(y - __bfloat162float(hy));
    hw = (uint32_t)__bfloat16_as_ushort(hx) | ((uint32_t)__bfloat16_as_ushort(hy) << 16);
    lw = (uint32_t)__bfloat16_as_ushort(lx) | ((uint32_t)__bfloat16_as_ushort(ly) << 16);
}

__global__ __launch_bounds__(256, 1)
void mma_gemm_bf16x3(const float* __restrict__ A, int lda,
                     const float* __restrict__ Bt,      // [N,K] row-major
                     const float* __restrict__ bias,
                     float* __restrict__ C, int ldc,
                     int M, int K, int ACC)
{
    extern __shared__ __align__(16) char smem[];
    const uint32_t sb = smem_u32(smem);

    const int tid  = threadIdx.x;
    const int lane = tid & 31;
    const int wid  = tid >> 5;
    const int bm   = blockIdx.y << 7;
    const int bn   = blockIdx.x << 7;
    const int wm   = (wid & 1) << 6;     // 0 or 64
    const int wn   = (wid >> 1) << 5;    // 0,32,64,96
    const int g    = lane >> 2;
    const int tg   = lane & 3;

    float acc[4][4][4];
#pragma unroll
    for (int mi = 0; mi < 4; ++mi)
#pragma unroll
        for (int ni = 0; ni < 4; ++ni)
#pragma unroll
            for (int q = 0; q < 4; ++q) acc[mi][ni][q] = 0.f;

    const int nc = K >> 5;

    // per-thread staging: 4 float4 of A + 4 float4 of B  (128x32 / 256 threads)
    float4 ra[4], rb[4];
    const int srow = tid >> 3;           // 0..31 (+32 per r)  [id = tid + 256r]
    const int sc4  = tid & 7;            // float4 column

    auto ldg = [&](int i) {
        const int kc = i << 5;
#pragma unroll
        for (int r = 0; r < 4; ++r) {
            int row = srow + (r << 5);
            bool ok = (bm + row) < M;
            const float* pa = A + (size_t)(bm + row) * lda + kc + (sc4 << 2);
            ra[r] = ok ? *(const float4*)pa : make_float4(0.f, 0.f, 0.f, 0.f);
            const float* pb = Bt + (size_t)(bn + row) * K + kc + (sc4 << 2);
            rb[r] = *(const float4*)pb;
        }
    };

    auto cvst = [&](int s) {
        const uint32_t base = sb + (uint32_t)s * STG_BY;
#pragma unroll
        for (int r = 0; r < 4; ++r) {
            int row = srow + (r << 5);
            uint32_t off = (uint32_t)(row * ROWB + (sc4 << 3));
            uint32_t h0, l0, h1, l1;
            cvt2(ra[r].x, ra[r].y, h0, l0);
            cvt2(ra[r].z, ra[r].w, h1, l1);
            asm volatile("st.shared.v2.b32 [%0], {%1,%2};" :: "r"(base + AH_OFF + off), "r"(h0), "r"(h1));
            asm volatile("st.shared.v2.b32 [%0], {%1,%2};" :: "r"(base + AL_OFF + off), "r"(l0), "r"(l1));
            cvt2(rb[r].x, rb[r].y, h0, l0);
            cvt2(rb[r].z, rb[r].w, h1, l1);
            asm volatile("st.shared.v2.b32 [%0], {%1,%2};" :: "r"(base + BH_OFF + off), "r"(h0), "r"(h1));
            asm volatile("st.shared.v2.b32 [%0], {%1,%2};" :: "r"(base + BL_OFF + off), "r"(l0), "r"(l1));
        }
    };

    // ldmatrix lane-address components
    const uint32_t a_off = (uint32_t)((lane & 15) * ROWB + ((lane >> 4) << 4));
    const uint32_t b_off = (uint32_t)((lane & 7) * ROWB + (((lane >> 3) & 1) << 4));

    ldg(0);
    for (int i = 0; i < nc; ++i) {
        const int s = i & 1;
        cvst(s);
        if (i + 1 < nc) ldg(i + 1);
        __syncthreads();

        const uint32_t stg = sb + (uint32_t)s * STG_BY;
#pragma unroll
        for (int k16 = 0; k16 < 2; ++k16) {
            const uint32_t kb = (uint32_t)(k16 << 5);       // 16 cols * 2B
            uint32_t bh[4][2], bl[4][2];
#pragma unroll
            for (int ni = 0; ni < 4; ++ni) {
                uint32_t ab = stg + BH_OFF + (uint32_t)((wn + (ni << 3)) * ROWB) + kb + b_off;
                LDM_X2(bh[ni][0], bh[ni][1], ab);
                LDM_X2(bl[ni][0], bl[ni][1], ab + (BL_OFF - BH_OFF));
            }
#pragma unroll
            for (int mi = 0; mi < 4; ++mi) {
                uint32_t ah[4], al[4];
                uint32_t aa = stg + AH_OFF + (uint32_t)((wm + (mi << 4)) * ROWB) + kb + a_off;
                LDM_X4(ah, aa);
                LDM_X4(al, aa + (AL_OFF - AH_OFF));
#pragma unroll
                for (int ni = 0; ni < 4; ++ni) {
                    MMA_B(acc[mi][ni], al, bh[ni][0], bh[ni][1]);
                    MMA_B(acc[mi][ni], ah, bl[ni][0], bl[ni][1]);
                    MMA_B(acc[mi][ni], ah, bh[ni][0], bh[ni][1]);
                }
            }
        }
        __syncthreads();
    }

    // ---- epilogue: bias add (+ optional accumulate into C) ----
#pragma unroll
    for (int mi = 0; mi < 4; ++mi) {
        int r0 = bm + wm + (mi << 4) + g;
#pragma unroll
        for (int ni = 0; ni < 4; ++ni) {
            int c0 = bn + wn + (ni << 3) + (tg << 1);
            float2 bv = *(const float2*)(bias + c0);
            if (r0 < M) {
                float* p = C + (size_t)r0 * ldc + c0;
                float2 o = make_float2(acc[mi][ni][0] + bv.x, acc[mi][ni][1] + bv.y);
                if (ACC) { float2 c = *(const float2*)p; o.x += c.x; o.y += c.y; }
                *(float2*)p = o;
            }
            if (r0 + 8 < M) {
                float* p = C + (size_t)(r0 + 8) * ldc + c0;
                float2 o = make_float2(acc[mi][ni][2] + bv.x, acc[mi][ni][3] + bv.y);
                if (ACC) { float2 c = *(const float2*)p; o.x += c.x; o.y += c.y; }
                *(float2*)p = o;
            }
        }
    }
}

// ---------------- BatchNorm ----------------
__global__ void colstats_kernel(const float* __restrict__ X, int C, double* __restrict__ sums) {
    int tid  = threadIdx.x;
    int nloc = C >> 8;
    double s[4] = {0, 0, 0, 0}, ss[4] = {0, 0, 0, 0};
    for (int r = blockIdx.x; r < NN; r += gridDim.x) {
        const float* row = X + (size_t)r * C;
        for (int i = 0; i < nloc; ++i) {
            float v = row[i * 256 + tid];
            s[i]  += (double)v;
            ss[i] += (double)v * (double)v;
        }
    }
    for (int i = 0; i < nloc; ++i) {
        atomicAdd(&sums[i * 256 + tid],      s[i]);
        atomicAdd(&sums[C + i * 256 + tid], ss[i]);
    }
}

__global__ void bncoef_kernel(const double* __restrict__ sums,
                              const float* __restrict__ g, const float* __restrict__ b,
                              int C, float* __restrict__ coef) {
    int c = blockIdx.x * blockDim.x + threadIdx.x;
    if (c >= C) return;
    double m  = sums[c] * (1.0 / NN);
    double v  = sums[C + c] * (1.0 / NN) - m * m;
    double sc = (double)g[c] / sqrt(v + 1e-5);
    coef[c]     = (float)sc;
    coef[C + c] = (float)((double)b[c] - m * sc);
}

__global__ void bnact_kernel(const float* __restrict__ X, int ldx,
                             float* __restrict__ Y, int ldy,
                             int C, const float* __restrict__ coef) {
    for (int r = blockIdx.x; r < NN; r += gridDim.x) {
        const float* xr = X + (size_t)r * ldx;
        float*       yr = Y + (size_t)r * ldy;
        for (int c = threadIdx.x; c < C; c += blockDim.x) {
            float y = fmaf(xr[c], coef[c], coef[C + c]);
            yr[c] = (y > 0.f) ? y : SLOPE * y;
        }
    }
}

// ---------------- driver ----------------
extern "C" void kernel_launch(void* const* d_in, const int* in_sizes, int n_in,
                              void* d_out, int out_size) {
    const float* x       = (const float*)d_in[0];
    const void*  ei      = d_in[1];
    const float* ew      = (const float*)d_in[2];
    const float* W_emb   = (const float*)d_in[3];
    const float* b_emb   = (const float*)d_in[4];
    const float* conv0_W = (const float*)d_in[5];
    const float* conv0_b = (const float*)d_in[6];
    const float* norm_g  = (const float*)d_in[7];
    const float* norm_b  = (const float*)d_in[8];
    const float* conv_W  = (const float*)d_in[9];
    const float* conv_b  = (const float*)d_in[10];
    const float* mlp_W1  = (const float*)d_in[11];
    const float* mlp_b1  = (const float*)d_in[12];
    const float* mlp_g   = (const float*)d_in[13];
    const float* mlp_bb  = (const float*)d_in[14];
    const float* mlp_W2  = (const float*)d_in[15];
    const float* mlp_b2  = (const float*)d_in[16];
    const float* W_out   = (const float*)d_in[17];
    const float* b_out   = (const float*)d_in[18];
    float* out = (float*)d_out;

    float *P, *h, *t, *zw, *Bt;
    int *deg, *fill;
    double* stats;
    float* coef;
    cudaGetSymbolAddress((void**)&P,     g_P);
    cudaGetSymbolAddress((void**)&h,     g_h);
    cudaGetSymbolAddress((void**)&t,     g_t);
    cudaGetSymbolAddress((void**)&zw,    g_zw);
    cudaGetSymbolAddress((void**)&Bt,    g_Bt);
    cudaGetSymbolAddress((void**)&deg,   g_deg);
    cudaGetSymbolAddress((void**)&fill,  g_fill);
    cudaGetSymbolAddress((void**)&stats, g_stats);
    cudaGetSymbolAddress((void**)&coef,  g_coef);

    cudaFuncSetAttribute(mma_gemm_bf16x3, cudaFuncAttributeMaxDynamicSharedMemorySize, GSM_TOTAL);

    const int MT = (NN + 127) / 128;   // 391 M-tiles
    dim3 blk256(256);
    dim3 spmm_blk(64, 4);
    dim3 spmm_grd(NN / 4);
    dim3 tb(32, 8);

    // ---- CSR build ----
    zero_words<<<(NN + 255) / 256, blk256>>>((unsigned*)deg, NN);
    zero_words<<<(NN + 255) / 256, blk256>>>((unsigned*)fill, NN);
    detect_kernel<<<1, 256>>>((const unsigned*)ei);
    hist_kernel<<<EE / 256, blk256>>>(ei);
    exscan_kernel<<<1, 1024>>>();
    scatter_kernel<<<EE / 256, blk256>>>(ei, ew);

    // ---- weight transposes into [N,K] ----
    transpose_kernel<<<dim3(HH / 32, CIN / 32), tb>>>(W_emb, Bt + OFF_EMB, CIN, HH);
    transpose_kernel<<<dim3(HH / 32, P_LD / 32), tb>>>(conv0_W, Bt + OFF_C0, P_LD, HH);
    for (int l = 0; l < 3; ++l) {
        transpose_kernel<<<dim3(HH / 32, P_LD / 32), tb>>>(
            conv_W + (size_t)l * P_LD * HH, Bt + OFF_CV + (size_t)l * P_LD * HH, P_LD, HH);
        transpose_kernel<<<dim3(H4 / 32, HH / 32), tb>>>(
            mlp_W1 + (size_t)l * HH * H4, Bt + OFF_W1 + (size_t)l * HH * H4, HH, H4);
        transpose_kernel<<<dim3(HH / 32, H4 / 32), tb>>>(
            mlp_W2 + (size_t)l * H4 * HH, Bt + OFF_W2 + (size_t)l * H4 * HH, H4, HH);
    }
    transpose_kernel<<<dim3(CIN / 32, HH / 32), tb>>>(W_out, Bt + OFF_OUT, HH, CIN);

    // ---- embed: h0 = x@W_emb + b_emb -> P[:,0:256] ----
    mma_gemm_bf16x3<<<dim3(HH / 128, MT), blk256, GSM_TOTAL>>>(
        x, CIN, Bt + OFF_EMB, b_emb, P, P_LD, NN, CIN, 0);
    spmm_kernel<<<spmm_grd, spmm_blk>>>(P, P + HH);
    spmm_kernel<<<spmm_grd, spmm_blk>>>(P + HH, P + 2 * HH);
    mma_gemm_bf16x3<<<dim3(HH / 128, MT), blk256, GSM_TOTAL>>>(
        P, P_LD, Bt + OFF_C0, conv0_b, h, HH, NN, P_LD, 0);

    for (int l = 0; l < 3; ++l) {
        zero_words<<<16, blk256>>>((unsigned*)stats, 4096);
        colstats_kernel<<<512, blk256>>>(h, HH, stats);
        bncoef_kernel<<<1, 256>>>(stats, norm_g + l * HH, norm_b + l * HH, HH, coef);
        bnact_kernel<<<2048, blk256>>>(h, HH, P, P_LD, HH, coef);
        spmm_kernel<<<spmm_grd, spmm_blk>>>(P, P + HH);
        spmm_kernel<<<spmm_grd, spmm_blk>>>(P + HH, P + 2 * HH);
        mma_gemm_bf16x3<<<dim3(HH / 128, MT), blk256, GSM_TOTAL>>>(
            P, P_LD, Bt + OFF_CV + (size_t)l * P_LD * HH, conv_b + l * HH, t, HH, NN, P_LD, 0);
        mma_gemm_bf16x3<<<dim3(H4 / 128, MT), blk256, GSM_TOTAL>>>(
            t, HH, Bt + OFF_W1 + (size_t)l * HH * H4, mlp_b1 + l * H4, zw, H4, NN, HH, 0);
        zero_words<<<16, blk256>>>((unsigned*)stats, 4096);
        colstats_kernel<<<512, blk256>>>(zw, H4, stats);
        bncoef_kernel<<<4, 256>>>(stats, mlp_g + l * H4, mlp_bb + l * H4, H4, coef);
        bnact_kernel<<<2048, blk256>>>(zw, H4, zw, H4, H4, coef);
        mma_gemm_bf16x3<<<dim3(HH / 128, MT), blk256, GSM_TOTAL>>>(
            zw, H4, Bt + OFF_W2 + (size_t)l * H4 * HH, mlp_b2 + l * HH, h, HH, NN, H4, 1);
    }

    mma_gemm_bf16x3<<<dim3(CIN / 128, MT), blk256, GSM_TOTAL>>>(
        h, HH, Bt + OFF_OUT, b_out, out, CIN, NN, HH, 0);
}

// round 11
// speedup vs baseline: 1.6956x; 1.0580x over previous
#include <cuda_runtime.h>
#include <cuda_bf16.h>
#include <cstdint>

typedef unsigned short u16;

// ---------------- problem constants ----------------
#define NN   50000
#define EE   800000
#define CIN  128
#define HH   256
#define H4   1024
#define P_LD 768            // [p0 | A p0 | A^2 p0] concatenated per row
#define SLOPE 0.01f

// ---------------- scratch (device globals; no runtime allocation) ----------------
__device__ float  g_P [(size_t)NN * P_LD];   // f32 P (cols 0..511 actually used)
__device__ float  g_h [(size_t)NN * HH];
__device__ float  g_zw[(size_t)NN * H4];
__device__ u16    g_Ph[(size_t)NN * P_LD];   // bf16 hi of P
__device__ u16    g_Pl[(size_t)NN * P_LD];   // bf16 lo of P
__device__ u16    g_th[(size_t)NN * HH];
__device__ u16    g_tl[(size_t)NN * HH];
__device__ u16    g_zh[(size_t)NN * H4];     // also reused for x-split
__device__ u16    g_zl[(size_t)NN * H4];
__device__ u16    g_Wh[2424832];
__device__ u16    g_Wl[2424832];
__device__ int    g_deg[NN];
__device__ int    g_fill[NN];
__device__ int    g_rowptr[NN + 1];
__device__ int    g_csrc[EE];
__device__ float  g_cw[EE];
__device__ double g_stats[2 * H4];
__device__ float  g_coef[2 * H4];
__device__ int    g_is64;

// transposed-weight offsets inside g_Wh/g_Wl
#define OFF_EMB  0          // 256x128
#define OFF_C0   32768      // 256x768
#define OFF_CV   229376     // 3 x 256x768
#define OFF_W1   819200     // 3 x 1024x256
#define OFF_W2   1605632    // 3 x 256x1024
#define OFF_OUT  2392064    // 128x256

// ---------------- helpers ----------------
__device__ __forceinline__ uint32_t smem_u32(const void* p) {
    uint32_t a;
    asm("{ .reg .u64 t; cvta.to.shared.u64 t, %1; cvt.u32.u64 %0, t; }" : "=r"(a) : "l"(p));
    return a;
}
// split x into bf16 hi + lo
__device__ __forceinline__ void split1(float x, u16& h, u16& l) {
    __nv_bfloat16 hb = __float2bfloat16(x);
    h = __bfloat16_as_ushort(hb);
    l = __bfloat16_as_ushort(__float2bfloat16(x - __bfloat162float(hb)));
}
// (x,y) -> packed hi word + lo word
__device__ __forceinline__ void cvt2(float x, float y, uint32_t& hw, uint32_t& lw) {
    u16 hx, lx, hy, ly;
    split1(x, hx, lx);
    split1(y, hy, ly);
    hw = (uint32_t)hx | ((uint32_t)hy << 16);
    lw = (uint32_t)lx | ((uint32_t)ly << 16);
}

// ---------------- utility ----------------
__global__ void zero_words(unsigned* p, int n) {
    int i = blockIdx.x * blockDim.x + threadIdx.x;
    if (i < n) p[i] = 0u;
}

__global__ void detect_kernel(const unsigned* p) {
    __shared__ unsigned sh[256];
    unsigned o = 0;
    for (int i = threadIdx.x; i < 2048; i += 256) o |= p[2 * i + 1];
    sh[threadIdx.x] = o;
    __syncthreads();
    for (int s = 128; s > 0; s >>= 1) {
        if (threadIdx.x < s) sh[threadIdx.x] |= sh[threadIdx.x + s];
        __syncthreads();
    }
    if (threadIdx.x == 0) g_is64 = (sh[0] == 0u) ? 1 : 0;
}

__device__ __forceinline__ int eidx(const void* p, long i) {
    return g_is64 ? (int)((const long long*)p)[i] : ((const int*)p)[i];
}

// ---------------- CSR build ----------------
__global__ void hist_kernel(const void* ei) {
    int e = blockIdx.x * 256 + threadIdx.x;
    if (e < EE) atomicAdd(&g_deg[eidx(ei, (long)EE + e)], 1);
}

__global__ void exscan_kernel() {
    __shared__ int sh[1024];
    __shared__ int carry;
    int tid = threadIdx.x;
    if (tid == 0) carry = 0;
    __syncthreads();
    for (int base = 0; base < NN; base += 1024) {
        int v = (base + tid < NN) ? g_deg[base + tid] : 0;
        sh[tid] = v;
        __syncthreads();
        for (int off = 1; off < 1024; off <<= 1) {
            int t = (tid >= off) ? sh[tid - off] : 0;
            __syncthreads();
            sh[tid] += t;
            __syncthreads();
        }
        if (base + tid < NN) g_rowptr[base + tid] = carry + sh[tid] - v;
        int total = sh[1023];
        __syncthreads();
        if (tid == 0) carry += total;
        __syncthreads();
    }
    if (tid == 0) g_rowptr[NN] = carry;
}

__global__ void scatter_kernel(const void* ei, const float* __restrict__ ew) {
    int e = blockIdx.x * 256 + threadIdx.x;
    if (e < EE) {
        int d = eidx(ei, (long)EE + e);
        int pos = g_rowptr[d] + atomicAdd(&g_fill[d], 1);
        g_csrc[pos] = eidx(ei, e);
        g_cw[pos]   = ew[e];
    }
}

// ---------------- SpMM (optionally emits f32 and/or bf16 hi/lo) ----------------
__global__ void spmm_kernel(const float* __restrict__ in, float* __restrict__ of,
                            u16* __restrict__ oh, u16* __restrict__ ol) {
    int row = blockIdx.x * 4 + threadIdx.y;
    int c   = threadIdx.x << 2;
    int beg = g_rowptr[row];
    int end = g_rowptr[row + 1];
    float4 acc = make_float4(0.f, 0.f, 0.f, 0.f);
    int e = beg;
    for (; e + 1 < end; e += 2) {
        int   s0 = g_csrc[e],   s1 = g_csrc[e + 1];
        float w0 = g_cw[e],     w1 = g_cw[e + 1];
        float4 v0 = *(const float4*)(in + (size_t)s0 * P_LD + c);
        float4 v1 = *(const float4*)(in + (size_t)s1 * P_LD + c);
        acc.x += w0 * v0.x + w1 * v1.x;
        acc.y += w0 * v0.y + w1 * v1.y;
        acc.z += w0 * v0.z + w1 * v1.z;
        acc.w += w0 * v0.w + w1 * v1.w;
    }
    if (e < end) {
        int s0 = g_csrc[e]; float w0 = g_cw[e];
        float4 v0 = *(const float4*)(in + (size_t)s0 * P_LD + c);
        acc.x += w0 * v0.x; acc.y += w0 * v0.y; acc.z += w0 * v0.z; acc.w += w0 * v0.w;
    }
    size_t o = (size_t)row * P_LD + c;
    if (of) *(float4*)(of + o) = acc;
    uint32_t h0, l0, h1, l1;
    cvt2(acc.x, acc.y, h0, l0);
    cvt2(acc.z, acc.w, h1, l1);
    *(uint2*)(oh + o) = make_uint2(h0, h1);
    *(uint2*)(ol + o) = make_uint2(l0, l1);
}

// ---------------- weight transpose + split: in[K,N] -> hi/lo [N,K] ----------------
__global__ void transpose_split(const float* __restrict__ in, u16* __restrict__ oh,
                                u16* __restrict__ ol, int K, int N) {
    __shared__ float t[32][33];
    int n0 = blockIdx.x << 5, k0 = blockIdx.y << 5;
    int tx = threadIdx.x, ty = threadIdx.y;
#pragma unroll
    for (int r = 0; r < 32; r += 8)
        t[ty + r][tx] = in[(size_t)(k0 + ty + r) * N + n0 + tx];
    __syncthreads();
#pragma unroll
    for (int r = 0; r < 32; r += 8) {
        u16 h, l;
        split1(t[tx][ty + r], h, l);
        size_t o = (size_t)(n0 + ty + r) * K + k0 + tx;
        oh[o] = h;
        ol[o] = l;
    }
}

// ---------------- activation split: f32 -> bf16 hi/lo ----------------
__global__ void split_act(const float* __restrict__ X, u16* __restrict__ Xh,
                          u16* __restrict__ Xl, int n4) {
    int i = blockIdx.x * 256 + threadIdx.x;
    if (i < n4) {
        float4 v = *(const float4*)(X + (size_t)i * 4);
        uint32_t h0, l0, h1, l1;
        cvt2(v.x, v.y, h0, l0);
        cvt2(v.z, v.w, h1, l1);
        *(uint2*)(Xh + (size_t)i * 4) = make_uint2(h0, h1);
        *(uint2*)(Xl + (size_t)i * 4) = make_uint2(l0, l1);
    }
}

// ---------------- mma.sync bf16x3 GEMM (pre-split operands) ----------------
// C = (ACC? C:0) + A@Bt^T + bias. A: hi/lo [M,K] bf16, B: hi/lo [N,K] bf16.
// Writes f32 C (if C) and/or bf16 hi/lo (if Ch). 128x128 CTA tile, BK=32,
// cp.async double buffer, 8 warps 64x32, ldmatrix (80B rows, conflict-free).
#define ROWB    80
#define TILE_B  (128 * ROWB)           // 10240 B
#define AH_OFF  0
#define AL_OFF  TILE_B
#define BH_OFF  (2 * TILE_B)
#define BL_OFF  (3 * TILE_B)
#define STG_BY  (4 * TILE_B)           // 40960 B
#define GSM_TOTAL (2 * STG_BY)         // 81920 B

#define MMA_B(d, a, b0, b1) \
    asm volatile("mma.sync.aligned.m16n8k16.row.col.f32.bf16.bf16.f32 " \
        "{%0,%1,%2,%3}, {%4,%5,%6,%7}, {%8,%9}, {%0,%1,%2,%3};" \
        : "+f"((d)[0]), "+f"((d)[1]), "+f"((d)[2]), "+f"((d)[3]) \
        : "r"((a)[0]), "r"((a)[1]), "r"((a)[2]), "r"((a)[3]), "r"(b0), "r"(b1))

#define LDM_X4(r, addr) \
    asm volatile("ldmatrix.sync.aligned.m8n8.x4.shared.b16 {%0,%1,%2,%3}, [%4];" \
        : "=r"((r)[0]), "=r"((r)[1]), "=r"((r)[2]), "=r"((r)[3]) : "r"(addr))

#define LDM_X2(r0, r1, addr) \
    asm volatile("ldmatrix.sync.aligned.m8n8.x2.shared.b16 {%0,%1}, [%2];" \
        : "=r"(r0), "=r"(r1) : "r"(addr))

__global__ __launch_bounds__(256)
void gemm_bf3(const u16* __restrict__ Ah, const u16* __restrict__ Al, int lda,
              const u16* __restrict__ Bh, const u16* __restrict__ Bl,
              const float* __restrict__ bias,
              float* __restrict__ C, int ldc, int ACC,
              u16* __restrict__ Ch, u16* __restrict__ Cl, int ldhl,
              int M, int K)
{
    extern __shared__ __align__(16) char smem[];
    const uint32_t sb = smem_u32(smem);

    const int tid  = threadIdx.x;
    const int lane = tid & 31;
    const int wid  = tid >> 5;
    const int bm   = blockIdx.y << 7;
    const int bn   = blockIdx.x << 7;
    const int wm   = (wid & 1) << 6;
    const int wn   = (wid >> 1) << 5;
    const int g    = lane >> 2;
    const int tg   = lane & 3;

    float acc[4][4][4];
#pragma unroll
    for (int mi = 0; mi < 4; ++mi)
#pragma unroll
        for (int ni = 0; ni < 4; ++ni)
#pragma unroll
            for (int q = 0; q < 4; ++q) acc[mi][ni][q] = 0.f;

    const int nc = K >> 5;

    // cp.async: each thread loads 2x16B per operand tile (128 rows x 64B)
    const int srow = tid >> 1;                 // 0..127
    const int sc   = (tid & 1) << 1;           // chunk base 0 or 2
    const int arow = (bm + srow < M) ? (bm + srow) : (M - 1);
    const int aok  = (bm + srow < M) ? 16 : 0;
    const u16* pa_h = Ah + (size_t)arow * lda;
    const u16* pa_l = Al + (size_t)arow * lda;
    const u16* pb_h = Bh + (size_t)(bn + srow) * K;
    const u16* pb_l = Bl + (size_t)(bn + srow) * K;

    auto prefetch = [&](int i) {
        const int s  = i & 1;
        const int ke = i << 5;                 // element offset into row
        const uint32_t base = sb + (uint32_t)s * STG_BY;
#pragma unroll
        for (int j = 0; j < 2; ++j) {
            const int c = sc + j;
            const uint32_t dst = base + (uint32_t)(srow * ROWB + c * 16);
            const int eo = ke + (c << 3);      // elements
            asm volatile("cp.async.ca.shared.global [%0], [%1], 16, %2;"
                         :: "r"(dst + AH_OFF), "l"(pa_h + eo), "r"(aok));
            asm volatile("cp.async.ca.shared.global [%0], [%1], 16, %2;"
                         :: "r"(dst + AL_OFF), "l"(pa_l + eo), "r"(aok));
            asm volatile("cp.async.ca.shared.global [%0], [%1], 16;"
                         :: "r"(dst + BH_OFF), "l"(pb_h + eo));
            asm volatile("cp.async.ca.shared.global [%0], [%1], 16;"
                         :: "r"(dst + BL_OFF), "l"(pb_l + eo));
        }
        asm volatile("cp.async.commit_group;" ::: "memory");
    };

    const uint32_t a_off = (uint32_t)((lane & 15) * ROWB + ((lane >> 4) << 4));
    const uint32_t b_off = (uint32_t)((lane & 7) * ROWB + (((lane >> 3) & 1) << 4));

    prefetch(0);
    for (int i = 0; i < nc; ++i) {
        if (i + 1 < nc) {
            prefetch(i + 1);
            asm volatile("cp.async.wait_group 1;" ::: "memory");
        } else {
            asm volatile("cp.async.wait_group 0;" ::: "memory");
        }
        __syncthreads();

        const uint32_t stg = sb + (uint32_t)(i & 1) * STG_BY;
#pragma unroll
        for (int k16 = 0; k16 < 2; ++k16) {
            const uint32_t kb = (uint32_t)(k16 << 5);
            uint32_t bh[4][2], bl[4][2];
#pragma unroll
            for (int ni = 0; ni < 4; ++ni) {
                uint32_t ab = stg + BH_OFF + (uint32_t)((wn + (ni << 3)) * ROWB) + kb + b_off;
                LDM_X2(bh[ni][0], bh[ni][1], ab);
                LDM_X2(bl[ni][0], bl[ni][1], ab + (BL_OFF - BH_OFF));
            }
#pragma unroll
            for (int mi = 0; mi < 4; ++mi) {
                uint32_t ah[4], al[4];
                uint32_t aa = stg + AH_OFF + (uint32_t)((wm + (mi << 4)) * ROWB) + kb + a_off;
                LDM_X4(ah, aa);
                LDM_X4(al, aa + (AL_OFF - AH_OFF));
#pragma unroll
                for (int ni = 0; ni < 4; ++ni) {
                    MMA_B(acc[mi][ni], al, bh[ni][0], bh[ni][1]);
                    MMA_B(acc[mi][ni], ah, bl[ni][0], bl[ni][1]);
                    MMA_B(acc[mi][ni], ah, bh[ni][0], bh[ni][1]);
                }
            }
        }
        __syncthreads();
    }

    // ---- epilogue ----
#pragma unroll
    for (int mi = 0; mi < 4; ++mi) {
#pragma unroll
        for (int ni = 0; ni < 4; ++ni) {
            int c0 = bn + wn + (ni << 3) + (tg << 1);
            float2 bv = *(const float2*)(bias + c0);
#pragma unroll
            for (int half = 0; half < 2; ++half) {
                int r = bm + wm + (mi << 4) + g + (half << 3);
                if (r >= M) continue;
                float ox = acc[mi][ni][half * 2 + 0] + bv.x;
                float oy = acc[mi][ni][half * 2 + 1] + bv.y;
                if (C) {
                    float* p = C + (size_t)r * ldc + c0;
                    if (ACC) { ox += p[0]; oy += p[1]; }
                    p[0] = ox; p[1] = oy;
                }
                if (Ch) {
                    uint32_t hw, lw;
                    cvt2(ox, oy, hw, lw);
                    *(uint32_t*)(Ch + (size_t)r * ldhl + c0) = hw;
                    *(uint32_t*)(Cl + (size_t)r * ldhl + c0) = lw;
                }
            }
        }
    }
}

// ---------------- BatchNorm ----------------
__global__ void colstats_kernel(const float* __restrict__ X, int C, double* __restrict__ sums) {
    int tid  = threadIdx.x;
    int nloc = C >> 8;
    double s[4] = {0, 0, 0, 0}, ss[4] = {0, 0, 0, 0};
    for (int r = blockIdx.x; r < NN; r += gridDim.x) {
        const float* row = X + (size_t)r * C;
        for (int i = 0; i < nloc; ++i) {
            float v = row[i * 256 + tid];
            s[i]  += (double)v;
            ss[i] += (double)v * (double)v;
        }
    }
    for (int i = 0; i < nloc; ++i) {
        atomicAdd(&sums[i * 256 + tid],      s[i]);
        atomicAdd(&sums[C + i * 256 + tid], ss[i]);
    }
}

__global__ void bncoef_kernel(const double* __restrict__ sums,
                              const float* __restrict__ g, const float* __restrict__ b,
                              int C, float* __restrict__ coef) {
    int c = blockIdx.x * blockDim.x + threadIdx.x;
    if (c >= C) return;
    double m  = sums[c] * (1.0 / NN);
    double v  = sums[C + c] * (1.0 / NN) - m * m;
    double sc = (double)g[c] / sqrt(v + 1e-5);
    coef[c]     = (float)sc;
    coef[C + c] = (float)((double)b[c] - m * sc);
}

// BN + LeakyReLU; emits optional f32 (ld ldy) and bf16 hi/lo (ld ldy)
__global__ void bnact_split(const float* __restrict__ X, int ldx,
                            float* __restrict__ Yf, u16* __restrict__ Yh,
                            u16* __restrict__ Yl, int ldy,
                            int C, const float* __restrict__ coef) {
    int row = blockIdx.x * 4 + threadIdx.y;
    const float* xr = X + (size_t)row * ldx;
    size_t ob = (size_t)row * ldy;
    for (int c = threadIdx.x << 2; c < C; c += 256) {
        float4 v  = *(const float4*)(xr + c);
        float4 sc = *(const float4*)(coef + c);
        float4 sh = *(const float4*)(coef + C + c);
        float4 y;
        y.x = fmaf(v.x, sc.x, sh.x); y.x = (y.x > 0.f) ? y.x : SLOPE * y.x;
        y.y = fmaf(v.y, sc.y, sh.y); y.y = (y.y > 0.f) ? y.y : SLOPE * y.y;
        y.z = fmaf(v.z, sc.z, sh.z); y.z = (y.z > 0.f) ? y.z : SLOPE * y.z;
        y.w = fmaf(v.w, sc.w, sh.w); y.w = (y.w > 0.f) ? y.w : SLOPE * y.w;
        if (Yf) *(float4*)(Yf + ob + c) = y;
        uint32_t h0, l0, h1, l1;
        cvt2(y.x, y.y, h0, l0);
        cvt2(y.z, y.w, h1, l1);
        *(uint2*)(Yh + ob + c) = make_uint2(h0, h1);
        *(uint2*)(Yl + ob + c) = make_uint2(l0, l1);
    }
}

// ---------------- driver ----------------
extern "C" void kernel_launch(void* const* d_in, const int* in_sizes, int n_in,
                              void* d_out, int out_size) {
    const float* x       = (const float*)d_in[0];
    const void*  ei      = d_in[1];
    const float* ew      = (const float*)d_in[2];
    const float* W_emb   = (const float*)d_in[3];
    const float* b_emb   = (const float*)d_in[4];
    const float* conv0_W = (const float*)d_in[5];
    const float* conv0_b = (const float*)d_in[6];
    const float* norm_g  = (const float*)d_in[7];
    const float* norm_b  = (const float*)d_in[8];
    const float* conv_W  = (const float*)d_in[9];
    const float* conv_b  = (const float*)d_in[10];
    const float* mlp_W1  = (const float*)d_in[11];
    const float* mlp_b1  = (const float*)d_in[12];
    const float* mlp_g   = (const float*)d_in[13];
    const float* mlp_bb  = (const float*)d_in[14];
    const float* mlp_W2  = (const float*)d_in[15];
    const float* mlp_b2  = (const float*)d_in[16];
    const float* W_out   = (const float*)d_in[17];
    const float* b_out   = (const float*)d_in[18];
    float* out = (float*)d_out;

    float *P, *h, *zw;
    u16 *Ph, *Pl, *th, *tl, *zh, *zl, *Wh, *Wl;
    int *deg, *fill;
    double* stats;
    float* coef;
    cudaGetSymbolAddress((void**)&P,     g_P);
    cudaGetSymbolAddress((void**)&h,     g_h);
    cudaGetSymbolAddress((void**)&zw,    g_zw);
    cudaGetSymbolAddress((void**)&Ph,    g_Ph);
    cudaGetSymbolAddress((void**)&Pl,    g_Pl);
    cudaGetSymbolAddress((void**)&th,    g_th);
    cudaGetSymbolAddress((void**)&tl,    g_tl);
    cudaGetSymbolAddress((void**)&zh,    g_zh);
    cudaGetSymbolAddress((void**)&zl,    g_zl);
    cudaGetSymbolAddress((void**)&Wh,    g_Wh);
    cudaGetSymbolAddress((void**)&Wl,    g_Wl);
    cudaGetSymbolAddress((void**)&deg,   g_deg);
    cudaGetSymbolAddress((void**)&fill,  g_fill);
    cudaGetSymbolAddress((void**)&stats, g_stats);
    cudaGetSymbolAddress((void**)&coef,  g_coef);

    cudaFuncSetAttribute(gemm_bf3, cudaFuncAttributeMaxDynamicSharedMemorySize, GSM_TOTAL);

    const int MT = (NN + 127) / 128;   // 391 M-tiles
    dim3 blk256(256);
    dim3 spmm_blk(64, 4);
    dim3 spmm_grd(NN / 4);
    dim3 bn_blk(64, 4);
    dim3 bn_grd(NN / 4);
    dim3 tb(32, 8);

    // ---- CSR build ----
    zero_words<<<(NN + 255) / 256, blk256>>>((unsigned*)deg, NN);
    zero_words<<<(NN + 255) / 256, blk256>>>((unsigned*)fill, NN);
    detect_kernel<<<1, 256>>>((const unsigned*)ei);
    hist_kernel<<<EE / 256, blk256>>>(ei);
    exscan_kernel<<<1, 1024>>>();
    scatter_kernel<<<EE / 256, blk256>>>(ei, ew);

    // ---- weight transpose + split ----
    transpose_split<<<dim3(HH / 32, CIN / 32), tb>>>(W_emb, Wh + OFF_EMB, Wl + OFF_EMB, CIN, HH);
    transpose_split<<<dim3(HH / 32, P_LD / 32), tb>>>(conv0_W, Wh + OFF_C0, Wl + OFF_C0, P_LD, HH);
    for (int l = 0; l < 3; ++l) {
        transpose_split<<<dim3(HH / 32, P_LD / 32), tb>>>(
            conv_W + (size_t)l * P_LD * HH, Wh + OFF_CV + (size_t)l * P_LD * HH,
            Wl + OFF_CV + (size_t)l * P_LD * HH, P_LD, HH);
        transpose_split<<<dim3(H4 / 32, HH / 32), tb>>>(
            mlp_W1 + (size_t)l * HH * H4, Wh + OFF_W1 + (size_t)l * HH * H4,
            Wl + OFF_W1 + (size_t)l * HH * H4, HH, H4);
        transpose_split<<<dim3(HH / 32, H4 / 32), tb>>>(
            mlp_W2 + (size_t)l * H4 * HH, Wh + OFF_W2 + (size_t)l * H4 * HH,
            Wl + OFF_W2 + (size_t)l * H4 * HH, H4, HH);
    }
    transpose_split<<<dim3(CIN / 32, HH / 32), tb>>>(W_out, Wh + OFF_OUT, Wl + OFF_OUT, HH, CIN);

    // ---- split x (into zh/zl, free until first bnact(zw)) ----
    split_act<<<(NN * CIN / 4 + 255) / 256, blk256>>>(x, zh, zl, NN * CIN / 4);

    // ---- embed: P[:,0:256] = x@W_emb + b_emb  (f32 + hi/lo) ----
    gemm_bf3<<<dim3(HH / 128, MT), blk256, GSM_TOTAL>>>(
        zh, zl, CIN, Wh + OFF_EMB, Wl + OFF_EMB, b_emb,
        P, P_LD, 0, Ph, Pl, P_LD, NN, CIN);
    spmm_kernel<<<spmm_grd, spmm_blk>>>(P, P + HH, Ph + HH, Pl + HH);
    spmm_kernel<<<spmm_grd, spmm_blk>>>(P + HH, nullptr, Ph + 2 * HH, Pl + 2 * HH);
    // conv0: h = P@[W0;W1;W2] + b  (f32 only)
    gemm_bf3<<<dim3(HH / 128, MT), blk256, GSM_TOTAL>>>(
        Ph, Pl, P_LD, Wh + OFF_C0, Wl + OFF_C0, conv0_b,
        h, HH, 0, nullptr, nullptr, 0, NN, P_LD);

    for (int l = 0; l < 3; ++l) {
        // z1 = lrelu(BN(h)) -> P cols 0..255 (f32 for spmm + hi/lo for conv GEMM)
        zero_words<<<16, blk256>>>((unsigned*)stats, 4096);
        colstats_kernel<<<512, blk256>>>(h, HH, stats);
        bncoef_kernel<<<1, 256>>>(stats, norm_g + l * HH, norm_b + l * HH, HH, coef);
        bnact_split<<<bn_grd, bn_blk>>>(h, HH, P, Ph, Pl, P_LD, HH, coef);
        spmm_kernel<<<spmm_grd, spmm_blk>>>(P, P + HH, Ph + HH, Pl + HH);
        spmm_kernel<<<spmm_grd, spmm_blk>>>(P + HH, nullptr, Ph + 2 * HH, Pl + 2 * HH);
        // t = P @ convW_l + conv_b  (hi/lo only — feeds W1 GEMM directly)
        gemm_bf3<<<dim3(HH / 128, MT), blk256, GSM_TOTAL>>>(
            Ph, Pl, P_LD, Wh + OFF_CV + (size_t)l * P_LD * HH,
            Wl + OFF_CV + (size_t)l * P_LD * HH, conv_b + l * HH,
            nullptr, 0, 0, th, tl, HH, NN, P_LD);
        // zw = t @ W1 + b1  (f32 for BN stats)
        gemm_bf3<<<dim3(H4 / 128, MT), blk256, GSM_TOTAL>>>(
            th, tl, HH, Wh + OFF_W1 + (size_t)l * HH * H4,
            Wl + OFF_W1 + (size_t)l * HH * H4, mlp_b1 + l * H4,
            zw, H4, 0, nullptr, nullptr, 0, NN, HH);
        // lrelu(BN(zw)) -> zh/zl (hi/lo only)
        zero_words<<<16, blk256>>>((unsigned*)stats, 4096);
        colstats_kernel<<<512, blk256>>>(zw, H4, stats);
        bncoef_kernel<<<4, 256>>>(stats, mlp_g + l * H4, mlp_bb + l * H4, H4, coef);
        bnact_split<<<bn_grd, bn_blk>>>(zw, H4, nullptr, zh, zl, H4, H4, coef);
        // h += z @ W2 + b2
        gemm_bf3<<<dim3(HH / 128, MT), blk256, GSM_TOTAL>>>(
            zh, zl, H4, Wh + OFF_W2 + (size_t)l * H4 * HH,
            Wl + OFF_W2 + (size_t)l * H4 * HH, mlp_b2 + l * HH,
            h, HH, 1, nullptr, nullptr, 0, NN, H4);
    }

    // ---- out = h @ W_out + b_out ----
    split_act<<<(NN * HH / 4 + 255) / 256, blk256>>>(h, th, tl, NN * HH / 4);
    gemm_bf3<<<dim3(CIN / 128, MT), blk256, GSM_TOTAL>>>(
        th, tl, HH, Wh + OFF_OUT, Wl + OFF_OUT, b_out,
        out, CIN, 0, nullptr, nullptr, 0, NN, HH);
}

// round 12
// speedup vs baseline: 1.7615x; 1.0389x over previous
#include <cuda_runtime.h>
#include <cuda_bf16.h>
#include <cstdint>

typedef unsigned short u16;

// ---------------- problem constants ----------------
#define NN   50000
#define EE   800000
#define CIN  128
#define HH   256
#define H4   1024
#define P_LD 768            // [p0 | A p0 | A^2 p0] concatenated per row
#define SLOPE 0.01f

// ---------------- scratch (device globals; no runtime allocation) ----------------
__device__ float  g_P [(size_t)NN * P_LD];   // f32 P (cols 0..511 actually used)
__device__ float  g_h [(size_t)NN * HH];
__device__ float  g_zw[(size_t)NN * H4];
__device__ u16    g_Ph[(size_t)NN * P_LD];   // bf16 hi of P
__device__ u16    g_Pl[(size_t)NN * P_LD];   // bf16 lo of P
__device__ u16    g_th[(size_t)NN * HH];
__device__ u16    g_tl[(size_t)NN * HH];
__device__ u16    g_zh[(size_t)NN * H4];     // also reused for x-split
__device__ u16    g_zl[(size_t)NN * H4];
__device__ u16    g_Wh[2424832];
__device__ u16    g_Wl[2424832];
__device__ int    g_deg[NN];
__device__ int    g_fill[NN];
__device__ int    g_rowptr[NN + 1];
__device__ int    g_csrc[EE];
__device__ float  g_cw[EE];
__device__ double g_stats[2 * H4];
__device__ float  g_coef[2 * H4];
__device__ int    g_is64;

// transposed-weight offsets inside g_Wh/g_Wl
#define OFF_EMB  0          // 256x128
#define OFF_C0   32768      // 256x768
#define OFF_CV   229376     // 3 x 256x768
#define OFF_W1   819200     // 3 x 1024x256
#define OFF_W2   1605632    // 3 x 256x1024
#define OFF_OUT  2392064    // 128x256

// ---------------- helpers ----------------
__device__ __forceinline__ uint32_t smem_u32(const void* p) {
    uint32_t a;
    asm("{ .reg .u64 t; cvta.to.shared.u64 t, %1; cvt.u32.u64 %0, t; }" : "=r"(a) : "l"(p));
    return a;
}
// split x into bf16 hi + lo
__device__ __forceinline__ void split1(float x, u16& h, u16& l) {
    __nv_bfloat16 hb = __float2bfloat16(x);
    h = __bfloat16_as_ushort(hb);
    l = __bfloat16_as_ushort(__float2bfloat16(x - __bfloat162float(hb)));
}
// (x,y) -> packed hi word + lo word
__device__ __forceinline__ void cvt2(float x, float y, uint32_t& hw, uint32_t& lw) {
    u16 hx, lx, hy, ly;
    split1(x, hx, lx);
    split1(y, hy, ly);
    hw = (uint32_t)hx | ((uint32_t)hy << 16);
    lw = (uint32_t)lx | ((uint32_t)ly << 16);
}

// ---------------- utility ----------------
__global__ void zero_words(unsigned* p, int n) {
    int i = blockIdx.x * blockDim.x + threadIdx.x;
    if (i < n) p[i] = 0u;
}

__global__ void detect_kernel(const unsigned* p) {
    __shared__ unsigned sh[256];
    unsigned o = 0;
    for (int i = threadIdx.x; i < 2048; i += 256) o |= p[2 * i + 1];
    sh[threadIdx.x] = o;
    __syncthreads();
    for (int s = 128; s > 0; s >>= 1) {
        if (threadIdx.x < s) sh[threadIdx.x] |= sh[threadIdx.x + s];
        __syncthreads();
    }
    if (threadIdx.x == 0) g_is64 = (sh[0] == 0u) ? 1 : 0;
}

__device__ __forceinline__ int eidx(const void* p, long i) {
    return g_is64 ? (int)((const long long*)p)[i] : ((const int*)p)[i];
}

// ---------------- CSR build ----------------
__global__ void hist_kernel(const void* ei) {
    int e = blockIdx.x * 256 + threadIdx.x;
    if (e < EE) atomicAdd(&g_deg[eidx(ei, (long)EE + e)], 1);
}

__global__ void exscan_kernel() {
    __shared__ int sh[1024];
    __shared__ int carry;
    int tid = threadIdx.x;
    if (tid == 0) carry = 0;
    __syncthreads();
    for (int base = 0; base < NN; base += 1024) {
        int v = (base + tid < NN) ? g_deg[base + tid] : 0;
        sh[tid] = v;
        __syncthreads();
        for (int off = 1; off < 1024; off <<= 1) {
            int t = (tid >= off) ? sh[tid - off] : 0;
            __syncthreads();
            sh[tid] += t;
            __syncthreads();
        }
        if (base + tid < NN) g_rowptr[base + tid] = carry + sh[tid] - v;
        int total = sh[1023];
        __syncthreads();
        if (tid == 0) carry += total;
        __syncthreads();
    }
    if (tid == 0) g_rowptr[NN] = carry;
}

__global__ void scatter_kernel(const void* ei, const float* __restrict__ ew) {
    int e = blockIdx.x * 256 + threadIdx.x;
    if (e < EE) {
        int d = eidx(ei, (long)EE + e);
        int pos = g_rowptr[d] + atomicAdd(&g_fill[d], 1);
        g_csrc[pos] = eidx(ei, e);
        g_cw[pos]   = ew[e];
    }
}

// ---------------- SpMM (emits f32 optionally, bf16 hi/lo always) ----------------
__global__ void spmm_kernel(const float* __restrict__ in, float* __restrict__ of,
                            u16* __restrict__ oh, u16* __restrict__ ol) {
    int row = blockIdx.x * 4 + threadIdx.y;
    int c   = threadIdx.x << 2;
    int beg = g_rowptr[row];
    int end = g_rowptr[row + 1];
    float4 acc = make_float4(0.f, 0.f, 0.f, 0.f);
    int e = beg;
    for (; e + 1 < end; e += 2) {
        int   s0 = g_csrc[e],   s1 = g_csrc[e + 1];
        float w0 = g_cw[e],     w1 = g_cw[e + 1];
        float4 v0 = *(const float4*)(in + (size_t)s0 * P_LD + c);
        float4 v1 = *(const float4*)(in + (size_t)s1 * P_LD + c);
        acc.x += w0 * v0.x + w1 * v1.x;
        acc.y += w0 * v0.y + w1 * v1.y;
        acc.z += w0 * v0.z + w1 * v1.z;
        acc.w += w0 * v0.w + w1 * v1.w;
    }
    if (e < end) {
        int s0 = g_csrc[e]; float w0 = g_cw[e];
        float4 v0 = *(const float4*)(in + (size_t)s0 * P_LD + c);
        acc.x += w0 * v0.x; acc.y += w0 * v0.y; acc.z += w0 * v0.z; acc.w += w0 * v0.w;
    }
    size_t o = (size_t)row * P_LD + c;
    if (of) *(float4*)(of + o) = acc;
    uint32_t h0, l0, h1, l1;
    cvt2(acc.x, acc.y, h0, l0);
    cvt2(acc.z, acc.w, h1, l1);
    *(uint2*)(oh + o) = make_uint2(h0, h1);
    *(uint2*)(ol + o) = make_uint2(l0, l1);
}

// ---------------- weight transpose + split: in[K,N] -> hi/lo [N,K] ----------------
__global__ void transpose_split(const float* __restrict__ in, u16* __restrict__ oh,
                                u16* __restrict__ ol, int K, int N) {
    __shared__ float t[32][33];
    int n0 = blockIdx.x << 5, k0 = blockIdx.y << 5;
    int tx = threadIdx.x, ty = threadIdx.y;
#pragma unroll
    for (int r = 0; r < 32; r += 8)
        t[ty + r][tx] = in[(size_t)(k0 + ty + r) * N + n0 + tx];
    __syncthreads();
#pragma unroll
    for (int r = 0; r < 32; r += 8) {
        u16 h, l;
        split1(t[tx][ty + r], h, l);
        size_t o = (size_t)(n0 + ty + r) * K + k0 + tx;
        oh[o] = h;
        ol[o] = l;
    }
}

// ---------------- activation split: f32 -> bf16 hi/lo ----------------
__global__ void split_act(const float* __restrict__ X, u16* __restrict__ Xh,
                          u16* __restrict__ Xl, int n4) {
    int i = blockIdx.x * 256 + threadIdx.x;
    if (i < n4) {
        float4 v = *(const float4*)(X + (size_t)i * 4);
        uint32_t h0, l0, h1, l1;
        cvt2(v.x, v.y, h0, l0);
        cvt2(v.z, v.w, h1, l1);
        *(uint2*)(Xh + (size_t)i * 4) = make_uint2(h0, h1);
        *(uint2*)(Xl + (size_t)i * 4) = make_uint2(l0, l1);
    }
}

// ---------------- mma.sync bf16x3 GEMM (pre-split operands) ----------------
// C = (ACC? C:0) + A@Bt^T + bias. A: hi/lo [M,K] bf16, B: hi/lo [N,K] bf16.
// Writes f32 C (if C) and/or bf16 hi/lo (if Ch). 128x128 CTA tile, BK=32,
// cp.async double buffer, 8 warps 64x32, ldmatrix (80B rows, conflict-free).
// __launch_bounds__(256, 2): cap regs at 128 so 2 CTAs/SM co-reside.
#define ROWB    80
#define TILE_B  (128 * ROWB)           // 10240 B
#define AH_OFF  0
#define AL_OFF  TILE_B
#define BH_OFF  (2 * TILE_B)
#define BL_OFF  (3 * TILE_B)
#define STG_BY  (4 * TILE_B)           // 40960 B
#define GSM_TOTAL (2 * STG_BY)         // 81920 B ; x2 CTAs = 160KB <= 228KB

#define MMA_B(d, a, b0, b1) \
    asm volatile("mma.sync.aligned.m16n8k16.row.col.f32.bf16.bf16.f32 " \
        "{%0,%1,%2,%3}, {%4,%5,%6,%7}, {%8,%9}, {%0,%1,%2,%3};" \
        : "+f"((d)[0]), "+f"((d)[1]), "+f"((d)[2]), "+f"((d)[3]) \
        : "r"((a)[0]), "r"((a)[1]), "r"((a)[2]), "r"((a)[3]), "r"(b0), "r"(b1))

#define LDM_X4(r, addr) \
    asm volatile("ldmatrix.sync.aligned.m8n8.x4.shared.b16 {%0,%1,%2,%3}, [%4];" \
        : "=r"((r)[0]), "=r"((r)[1]), "=r"((r)[2]), "=r"((r)[3]) : "r"(addr))

#define LDM_X2(r0, r1, addr) \
    asm volatile("ldmatrix.sync.aligned.m8n8.x2.shared.b16 {%0,%1}, [%2];" \
        : "=r"(r0), "=r"(r1) : "r"(addr))

__global__ __launch_bounds__(256, 2)
void gemm_bf3(const u16* __restrict__ Ah, const u16* __restrict__ Al, int lda,
              const u16* __restrict__ Bh, const u16* __restrict__ Bl,
              const float* __restrict__ bias,
              float* __restrict__ C, int ldc, int ACC,
              u16* __restrict__ Ch, u16* __restrict__ Cl, int ldhl,
              int M, int K)
{
    extern __shared__ __align__(16) char smem[];
    const uint32_t sb = smem_u32(smem);

    const int tid  = threadIdx.x;
    const int lane = tid & 31;
    const int wid  = tid >> 5;
    const int bm   = blockIdx.y << 7;
    const int bn   = blockIdx.x << 7;
    const int wm   = (wid & 1) << 6;
    const int wn   = (wid >> 1) << 5;
    const int g    = lane >> 2;
    const int tg   = lane & 3;

    float acc[4][4][4];
#pragma unroll
    for (int mi = 0; mi < 4; ++mi)
#pragma unroll
        for (int ni = 0; ni < 4; ++ni)
#pragma unroll
            for (int q = 0; q < 4; ++q) acc[mi][ni][q] = 0.f;

    const int nc = K >> 5;

    // cp.async: each thread loads 2x16B per operand tile (128 rows x 64B)
    const int srow = tid >> 1;                 // 0..127
    const int sc   = (tid & 1) << 1;           // chunk base 0 or 2
    const int arow = (bm + srow < M) ? (bm + srow) : (M - 1);
    const int aok  = (bm + srow < M) ? 16 : 0;
    const u16* pa_h = Ah + (size_t)arow * lda;
    const u16* pa_l = Al + (size_t)arow * lda;
    const u16* pb_h = Bh + (size_t)(bn + srow) * K;
    const u16* pb_l = Bl + (size_t)(bn + srow) * K;

    auto prefetch = [&](int i) {
        const int s  = i & 1;
        const int ke = i << 5;                 // element offset into row
        const uint32_t base = sb + (uint32_t)s * STG_BY;
#pragma unroll
        for (int j = 0; j < 2; ++j) {
            const int c = sc + j;
            const uint32_t dst = base + (uint32_t)(srow * ROWB + c * 16);
            const int eo = ke + (c << 3);      // elements
            asm volatile("cp.async.cg.shared.global [%0], [%1], 16, %2;"
                         :: "r"(dst + AH_OFF), "l"(pa_h + eo), "r"(aok));
            asm volatile("cp.async.cg.shared.global [%0], [%1], 16, %2;"
                         :: "r"(dst + AL_OFF), "l"(pa_l + eo), "r"(aok));
            asm volatile("cp.async.cg.shared.global [%0], [%1], 16;"
                         :: "r"(dst + BH_OFF), "l"(pb_h + eo));
            asm volatile("cp.async.cg.shared.global [%0], [%1], 16;"
                         :: "r"(dst + BL_OFF), "l"(pb_l + eo));
        }
        asm volatile("cp.async.commit_group;" ::: "memory");
    };

    const uint32_t a_off = (uint32_t)((lane & 15) * ROWB + ((lane >> 4) << 4));
    const uint32_t b_off = (uint32_t)((lane & 7) * ROWB + (((lane >> 3) & 1) << 4));

    prefetch(0);
    for (int i = 0; i < nc; ++i) {
        if (i + 1 < nc) {
            prefetch(i + 1);
            asm volatile("cp.async.wait_group 1;" ::: "memory");
        } else {
            asm volatile("cp.async.wait_group 0;" ::: "memory");
        }
        __syncthreads();

        const uint32_t stg = sb + (uint32_t)(i & 1) * STG_BY;
#pragma unroll
        for (int k16 = 0; k16 < 2; ++k16) {
            const uint32_t kb = (uint32_t)(k16 << 5);
            uint32_t bh[4][2], bl[4][2];
#pragma unroll
            for (int ni = 0; ni < 4; ++ni) {
                uint32_t ab = stg + BH_OFF + (uint32_t)((wn + (ni << 3)) * ROWB) + kb + b_off;
                LDM_X2(bh[ni][0], bh[ni][1], ab);
                LDM_X2(bl[ni][0], bl[ni][1], ab + (BL_OFF - BH_OFF));
            }
#pragma unroll
            for (int mi = 0; mi < 4; ++mi) {
                uint32_t ah[4], al[4];
                uint32_t aa = stg + AH_OFF + (uint32_t)((wm + (mi << 4)) * ROWB) + kb + a_off;
                LDM_X4(ah, aa);
                LDM_X4(al, aa + (AL_OFF - AH_OFF));
#pragma unroll
                for (int ni = 0; ni < 4; ++ni) {
                    MMA_B(acc[mi][ni], al, bh[ni][0], bh[ni][1]);
                    MMA_B(acc[mi][ni], ah, bl[ni][0], bl[ni][1]);
                    MMA_B(acc[mi][ni], ah, bh[ni][0], bh[ni][1]);
                }
            }
        }
        __syncthreads();
    }

    // ---- epilogue ----
#pragma unroll
    for (int mi = 0; mi < 4; ++mi) {
#pragma unroll
        for (int ni = 0; ni < 4; ++ni) {
            int c0 = bn + wn + (ni << 3) + (tg << 1);
            float2 bv = *(const float2*)(bias + c0);
#pragma unroll
            for (int half = 0; half < 2; ++half) {
                int r = bm + wm + (mi << 4) + g + (half << 3);
                if (r >= M) continue;
                float ox = acc[mi][ni][half * 2 + 0] + bv.x;
                float oy = acc[mi][ni][half * 2 + 1] + bv.y;
                if (C) {
                    float* p = C + (size_t)r * ldc + c0;
                    if (ACC) { ox += p[0]; oy += p[1]; }
                    p[0] = ox; p[1] = oy;
                }
                if (Ch) {
                    uint32_t hw, lw;
                    cvt2(ox, oy, hw, lw);
                    *(uint32_t*)(Ch + (size_t)r * ldhl + c0) = hw;
                    *(uint32_t*)(Cl + (size_t)r * ldhl + c0) = lw;
                }
            }
        }
    }
}

// ---------------- BatchNorm ----------------
__global__ void colstats_kernel(const float* __restrict__ X, int C, double* __restrict__ sums) {
    int tid  = threadIdx.x;
    int nloc = C >> 8;
    double s[4] = {0, 0, 0, 0}, ss[4] = {0, 0, 0, 0};
    for (int r = blockIdx.x; r < NN; r += gridDim.x) {
        const float* row = X + (size_t)r * C;
        for (int i = 0; i < nloc; ++i) {
            float v = row[i * 256 + tid];
            s[i]  += (double)v;
            ss[i] += (double)v * (double)v;
        }
    }
    for (int i = 0; i < nloc; ++i) {
        atomicAdd(&sums[i * 256 + tid],      s[i]);
        atomicAdd(&sums[C + i * 256 + tid], ss[i]);
    }
}

__global__ void bncoef_kernel(const double* __restrict__ sums,
                              const float* __restrict__ g, const float* __restrict__ b,
                              int C, float* __restrict__ coef) {
    int c = blockIdx.x * blockDim.x + threadIdx.x;
    if (c >= C) return;
    double m  = sums[c] * (1.0 / NN);
    double v  = sums[C + c] * (1.0 / NN) - m * m;
    double sc = (double)g[c] / sqrt(v + 1e-5);
    coef[c]     = (float)sc;
    coef[C + c] = (float)((double)b[c] - m * sc);
}

// BN + LeakyReLU; emits optional f32 and bf16 hi/lo
__global__ void bnact_split(const float* __restrict__ X, int ldx,
                            float* __restrict__ Yf, u16* __restrict__ Yh,
                            u16* __restrict__ Yl, int ldy,
                            int C, const float* __restrict__ coef) {
    int row = blockIdx.x * 4 + threadIdx.y;
    const float* xr = X + (size_t)row * ldx;
    size_t ob = (size_t)row * ldy;
    for (int c = threadIdx.x << 2; c < C; c += 256) {
        float4 v  = *(const float4*)(xr + c);
        float4 sc = *(const float4*)(coef + c);
        float4 sh = *(const float4*)(coef + C + c);
        float4 y;
        y.x = fmaf(v.x, sc.x, sh.x); y.x = (y.x > 0.f) ? y.x : SLOPE * y.x;
        y.y = fmaf(v.y, sc.y, sh.y); y.y = (y.y > 0.f) ? y.y : SLOPE * y.y;
        y.z = fmaf(v.z, sc.z, sh.z); y.z = (y.z > 0.f) ? y.z : SLOPE * y.z;
        y.w = fmaf(v.w, sc.w, sh.w); y.w = (y.w > 0.f) ? y.w : SLOPE * y.w;
        if (Yf) *(float4*)(Yf + ob + c) = y;
        uint32_t h0, l0, h1, l1;
        cvt2(y.x, y.y, h0, l0);
        cvt2(y.z, y.w, h1, l1);
        *(uint2*)(Yh + ob + c) = make_uint2(h0, h1);
        *(uint2*)(Yl + ob + c) = make_uint2(l0, l1);
    }
}

// ---------------- driver ----------------
extern "C" void kernel_launch(void* const* d_in, const int* in_sizes, int n_in,
                              void* d_out, int out_size) {
    const float* x       = (const float*)d_in[0];
    const void*  ei      = d_in[1];
    const float* ew      = (const float*)d_in[2];
    const float* W_emb   = (const float*)d_in[3];
    const float* b_emb   = (const float*)d_in[4];
    const float* conv0_W = (const float*)d_in[5];
    const float* conv0_b = (const float*)d_in[6];
    const float* norm_g  = (const float*)d_in[7];
    const float* norm_b  = (const float*)d_in[8];
    const float* conv_W  = (const float*)d_in[9];
    const float* conv_b  = (const float*)d_in[10];
    const float* mlp_W1  = (const float*)d_in[11];
    const float* mlp_b1  = (const float*)d_in[12];
    const float* mlp_g   = (const float*)d_in[13];
    const float* mlp_bb  = (const float*)d_in[14];
    const float* mlp_W2  = (const float*)d_in[15];
    const float* mlp_b2  = (const float*)d_in[16];
    const float* W_out   = (const float*)d_in[17];
    const float* b_out   = (const float*)d_in[18];
    float* out = (float*)d_out;

    float *P, *h, *zw;
    u16 *Ph, *Pl, *th, *tl, *zh, *zl, *Wh, *Wl;
    int *deg, *fill;
    double* stats;
    float* coef;
    cudaGetSymbolAddress((void**)&P,     g_P);
    cudaGetSymbolAddress((void**)&h,     g_h);
    cudaGetSymbolAddress((void**)&zw,    g_zw);
    cudaGetSymbolAddress((void**)&Ph,    g_Ph);
    cudaGetSymbolAddress((void**)&Pl,    g_Pl);
    cudaGetSymbolAddress((void**)&th,    g_th);
    cudaGetSymbolAddress((void**)&tl,    g_tl);
    cudaGetSymbolAddress((void**)&zh,    g_zh);
    cudaGetSymbolAddress((void**)&zl,    g_zl);
    cudaGetSymbolAddress((void**)&Wh,    g_Wh);
    cudaGetSymbolAddress((void**)&Wl,    g_Wl);
    cudaGetSymbolAddress((void**)&deg,   g_deg);
    cudaGetSymbolAddress((void**)&fill,  g_fill);
    cudaGetSymbolAddress((void**)&stats, g_stats);
    cudaGetSymbolAddress((void**)&coef,  g_coef);

    cudaFuncSetAttribute(gemm_bf3, cudaFuncAttributeMaxDynamicSharedMemorySize, GSM_TOTAL);

    const int MT = (NN + 127) / 128;   // 391 M-tiles
    dim3 blk256(256);
    dim3 spmm_blk(64, 4);
    dim3 spmm_grd(NN / 4);
    dim3 bn_blk(64, 4);
    dim3 bn_grd(NN / 4);
    dim3 tb(32, 8);

    // ---- CSR build ----
    zero_words<<<(NN + 255) / 256, blk256>>>((unsigned*)deg, NN);
    zero_words<<<(NN + 255) / 256, blk256>>>((unsigned*)fill, NN);
    detect_kernel<<<1, 256>>>((const unsigned*)ei);
    hist_kernel<<<EE / 256, blk256>>>(ei);
    exscan_kernel<<<1, 1024>>>();
    scatter_kernel<<<EE / 256, blk256>>>(ei, ew);

    // ---- weight transpose + split ----
    transpose_split<<<dim3(HH / 32, CIN / 32), tb>>>(W_emb, Wh + OFF_EMB, Wl + OFF_EMB, CIN, HH);
    transpose_split<<<dim3(HH / 32, P_LD / 32), tb>>>(conv0_W, Wh + OFF_C0, Wl + OFF_C0, P_LD, HH);
    for (int l = 0; l < 3; ++l) {
        transpose_split<<<dim3(HH / 32, P_LD / 32), tb>>>(
            conv_W + (size_t)l * P_LD * HH, Wh + OFF_CV + (size_t)l * P_LD * HH,
            Wl + OFF_CV + (size_t)l * P_LD * HH, P_LD, HH);
        transpose_split<<<dim3(H4 / 32, HH / 32), tb>>>(
            mlp_W1 + (size_t)l * HH * H4, Wh + OFF_W1 + (size_t)l * HH * H4,
            Wl + OFF_W1 + (size_t)l * HH * H4, HH, H4);
        transpose_split<<<dim3(HH / 32, H4 / 32), tb>>>(
            mlp_W2 + (size_t)l * H4 * HH, Wh + OFF_W2 + (size_t)l * H4 * HH,
            Wl + OFF_W2 + (size_t)l * H4 * HH, H4, HH);
    }
    transpose_split<<<dim3(CIN / 32, HH / 32), tb>>>(W_out, Wh + OFF_OUT, Wl + OFF_OUT, HH, CIN);

    // ---- split x (into zh/zl, free until first bnact(zw)) ----
    split_act<<<(NN * CIN / 4 + 255) / 256, blk256>>>(x, zh, zl, NN * CIN / 4);

    // ---- embed: P[:,0:256] = x@W_emb + b_emb  (f32 + hi/lo) ----
    gemm_bf3<<<dim3(HH / 128, MT), blk256, GSM_TOTAL>>>(
        zh, zl, CIN, Wh + OFF_EMB, Wl + OFF_EMB, b_emb,
        P, P_LD, 0, Ph, Pl, P_LD, NN, CIN);
    spmm_kernel<<<spmm_grd, spmm_blk>>>(P, P + HH, Ph + HH, Pl + HH);
    spmm_kernel<<<spmm_grd, spmm_blk>>>(P + HH, nullptr, Ph + 2 * HH, Pl + 2 * HH);
    // conv0: h = P@[W0;W1;W2] + b  (f32 only)
    gemm_bf3<<<dim3(HH / 128, MT), blk256, GSM_TOTAL>>>(
        Ph, Pl, P_LD, Wh + OFF_C0, Wl + OFF_C0, conv0_b,
        h, HH, 0, nullptr, nullptr, 0, NN, P_LD);

    for (int l = 0; l < 3; ++l) {
        // z1 = lrelu(BN(h)) -> P cols 0..255 (f32 for spmm + hi/lo for conv GEMM)
        zero_words<<<16, blk256>>>((unsigned*)stats, 4096);
        colstats_kernel<<<512, blk256>>>(h, HH, stats);
        bncoef_kernel<<<1, 256>>>(stats, norm_g + l * HH, norm_b + l * HH, HH, coef);
        bnact_split<<<bn_grd, bn_blk>>>(h, HH, P, Ph, Pl, P_LD, HH, coef);
        spmm_kernel<<<spmm_grd, spmm_blk>>>(P, P + HH, Ph + HH, Pl + HH);
        spmm_kernel<<<spmm_grd, spmm_blk>>>(P + HH, nullptr, Ph + 2 * HH, Pl + 2 * HH);
        // t = P @ convW_l + conv_b  (hi/lo only — feeds W1 GEMM directly)
        gemm_bf3<<<dim3(HH / 128, MT), blk256, GSM_TOTAL>>>(
            Ph, Pl, P_LD, Wh + OFF_CV + (size_t)l * P_LD * HH,
            Wl + OFF_CV + (size_t)l * P_LD * HH, conv_b + l * HH,
            nullptr, 0, 0, th, tl, HH, NN, P_LD);
        // zw = t @ W1 + b1  (f32 for BN stats)
        gemm_bf3<<<dim3(H4 / 128, MT), blk256, GSM_TOTAL>>>(
            th, tl, HH, Wh + OFF_W1 + (size_t)l * HH * H4,
            Wl + OFF_W1 + (size_t)l * HH * H4, mlp_b1 + l * H4,
            zw, H4, 0, nullptr, nullptr, 0, NN, HH);
        // lrelu(BN(zw)) -> zh/zl (hi/lo only)
        zero_words<<<16, blk256>>>((unsigned*)stats, 4096);
        colstats_kernel<<<512, blk256>>>(zw, H4, stats);
        bncoef_kernel<<<4, 256>>>(stats, mlp_g + l * H4, mlp_bb + l * H4, H4, coef);
        bnact_split<<<bn_grd, bn_blk>>>(zw, H4, nullptr, zh, zl, H4, H4, coef);
        // h += z @ W2 + b2
        gemm_bf3<<<dim3(HH / 128, MT), blk256, GSM_TOTAL>>>(
            zh, zl, H4, Wh + OFF_W2 + (size_t)l * H4 * HH,
            Wl + OFF_W2 + (size_t)l * H4 * HH, mlp_b2 + l * HH,
            h, HH, 1, nullptr, nullptr, 0, NN, H4);
    }

    // ---- out = h @ W_out + b_out ----
    split_act<<<(NN * HH / 4 + 255) / 256, blk256>>>(h, th, tl, NN * HH / 4);
    gemm_bf3<<<dim3(CIN / 128, MT), blk256, GSM_TOTAL>>>(
        th, tl, HH, Wh + OFF_OUT, Wl + OFF_OUT, b_out,
        out, CIN, 0, nullptr, nullptr, 0, NN, HH);
}

// round 13
// speedup vs baseline: 1.8630x; 1.0576x over previous
#include <cuda_runtime.h>
#include <cuda_bf16.h>
#include <cstdint>

typedef unsigned short u16;

// ---------------- problem constants ----------------
#define NN   50000
#define EE   800000
#define CIN  128
#define HH   256
#define H4   1024
#define P_LD 768            // [p0 | A p0 | A^2 p0] concatenated per row
#define SLOPE 0.01f

// ---------------- scratch (device globals; no runtime allocation) ----------------
__device__ float  g_P [(size_t)NN * P_LD];
__device__ float  g_h [(size_t)NN * HH];
__device__ float  g_zw[(size_t)NN * H4];
__device__ u16    g_Ph[(size_t)NN * P_LD];
__device__ u16    g_Pl[(size_t)NN * P_LD];
__device__ u16    g_th[(size_t)NN * HH];
__device__ u16    g_tl[(size_t)NN * HH];
__device__ u16    g_zh[(size_t)NN * H4];     // also reused for x-split
__device__ u16    g_zl[(size_t)NN * H4];
__device__ u16    g_Wh[2424832];
__device__ u16    g_Wl[2424832];
__device__ int    g_deg[NN];
__device__ int    g_fill[NN];
__device__ int    g_rowptr[NN + 1];
__device__ int    g_csrc[EE];
__device__ float  g_cw[EE];
__device__ double g_stats[2 * H4];
__device__ float  g_coef[2 * H4];
__device__ int    g_is64;

// transposed-weight offsets inside g_Wh/g_Wl
#define OFF_EMB  0          // 256x128
#define OFF_C0   32768      // 256x768
#define OFF_CV   229376     // 3 x 256x768
#define OFF_W1   819200     // 3 x 1024x256
#define OFF_W2   1605632    // 3 x 256x1024
#define OFF_OUT  2392064    // 128x256

// ---------------- helpers ----------------
__device__ __forceinline__ uint32_t smem_u32(const void* p) {
    uint32_t a;
    asm("{ .reg .u64 t; cvta.to.shared.u64 t, %1; cvt.u32.u64 %0, t; }" : "=r"(a) : "l"(p));
    return a;
}
__device__ __forceinline__ void split1(float x, u16& h, u16& l) {
    __nv_bfloat16 hb = __float2bfloat16(x);
    h = __bfloat16_as_ushort(hb);
    l = __bfloat16_as_ushort(__float2bfloat16(x - __bfloat162float(hb)));
}
__device__ __forceinline__ void cvt2(float x, float y, uint32_t& hw, uint32_t& lw) {
    u16 hx, lx, hy, ly;
    split1(x, hx, lx);
    split1(y, hy, ly);
    hw = (uint32_t)hx | ((uint32_t)hy << 16);
    lw = (uint32_t)lx | ((uint32_t)ly << 16);
}

// ---------------- utility ----------------
__global__ void zero_words(unsigned* p, int n) {
    int i = blockIdx.x * blockDim.x + threadIdx.x;
    if (i < n) p[i] = 0u;
}

__global__ void detect_kernel(const unsigned* p) {
    __shared__ unsigned sh[256];
    unsigned o = 0;
    for (int i = threadIdx.x; i < 2048; i += 256) o |= p[2 * i + 1];
    sh[threadIdx.x] = o;
    __syncthreads();
    for (int s = 128; s > 0; s >>= 1) {
        if (threadIdx.x < s) sh[threadIdx.x] |= sh[threadIdx.x + s];
        __syncthreads();
    }
    if (threadIdx.x == 0) g_is64 = (sh[0] == 0u) ? 1 : 0;
}

__device__ __forceinline__ int eidx(const void* p, long i) {
    return g_is64 ? (int)((const long long*)p)[i] : ((const int*)p)[i];
}

// ---------------- CSR build ----------------
__global__ void hist_kernel(const void* ei) {
    int e = blockIdx.x * 256 + threadIdx.x;
    if (e < EE) atomicAdd(&g_deg[eidx(ei, (long)EE + e)], 1);
}

__global__ void exscan_kernel() {
    __shared__ int sh[1024];
    __shared__ int carry;
    int tid = threadIdx.x;
    if (tid == 0) carry = 0;
    __syncthreads();
    for (int base = 0; base < NN; base += 1024) {
        int v = (base + tid < NN) ? g_deg[base + tid] : 0;
        sh[tid] = v;
        __syncthreads();
        for (int off = 1; off < 1024; off <<= 1) {
            int t = (tid >= off) ? sh[tid - off] : 0;
            __syncthreads();
            sh[tid] += t;
            __syncthreads();
        }
        if (base + tid < NN) g_rowptr[base + tid] = carry + sh[tid] - v;
        int total = sh[1023];
        __syncthreads();
        if (tid == 0) carry += total;
        __syncthreads();
    }
    if (tid == 0) g_rowptr[NN] = carry;
}

__global__ void scatter_kernel(const void* ei, const float* __restrict__ ew) {
    int e = blockIdx.x * 256 + threadIdx.x;
    if (e < EE) {
        int d = eidx(ei, (long)EE + e);
        int pos = g_rowptr[d] + atomicAdd(&g_fill[d], 1);
        g_csrc[pos] = eidx(ei, e);
        g_cw[pos]   = ew[e];
    }
}

// ---------------- SpMM (emits f32 optionally, bf16 hi/lo always) ----------------
__global__ void spmm_kernel(const float* __restrict__ in, float* __restrict__ of,
                            u16* __restrict__ oh, u16* __restrict__ ol) {
    int row = blockIdx.x * 4 + threadIdx.y;
    int c   = threadIdx.x << 2;
    int beg = g_rowptr[row];
    int end = g_rowptr[row + 1];
    float4 acc = make_float4(0.f, 0.f, 0.f, 0.f);
    int e = beg;
    for (; e + 1 < end; e += 2) {
        int   s0 = g_csrc[e],   s1 = g_csrc[e + 1];
        float w0 = g_cw[e],     w1 = g_cw[e + 1];
        float4 v0 = *(const float4*)(in + (size_t)s0 * P_LD + c);
        float4 v1 = *(const float4*)(in + (size_t)s1 * P_LD + c);
        acc.x += w0 * v0.x + w1 * v1.x;
        acc.y += w0 * v0.y + w1 * v1.y;
        acc.z += w0 * v0.z + w1 * v1.z;
        acc.w += w0 * v0.w + w1 * v1.w;
    }
    if (e < end) {
        int s0 = g_csrc[e]; float w0 = g_cw[e];
        float4 v0 = *(const float4*)(in + (size_t)s0 * P_LD + c);
        acc.x += w0 * v0.x; acc.y += w0 * v0.y; acc.z += w0 * v0.z; acc.w += w0 * v0.w;
    }
    size_t o = (size_t)row * P_LD + c;
    if (of) *(float4*)(of + o) = acc;
    uint32_t h0, l0, h1, l1;
    cvt2(acc.x, acc.y, h0, l0);
    cvt2(acc.z, acc.w, h1, l1);
    *(uint2*)(oh + o) = make_uint2(h0, h1);
    *(uint2*)(ol + o) = make_uint2(l0, l1);
}

// ---------------- weight transpose + split: in[K,N] -> hi/lo [N,K] ----------------
__global__ void transpose_split(const float* __restrict__ in, u16* __restrict__ oh,
                                u16* __restrict__ ol, int K, int N) {
    __shared__ float t[32][33];
    int n0 = blockIdx.x << 5, k0 = blockIdx.y << 5;
    int tx = threadIdx.x, ty = threadIdx.y;
#pragma unroll
    for (int r = 0; r < 32; r += 8)
        t[ty + r][tx] = in[(size_t)(k0 + ty + r) * N + n0 + tx];
    __syncthreads();
#pragma unroll
    for (int r = 0; r < 32; r += 8) {
        u16 h, l;
        split1(t[tx][ty + r], h, l);
        size_t o = (size_t)(n0 + ty + r) * K + k0 + tx;
        oh[o] = h;
        ol[o] = l;
    }
}

// ---------------- activation split: f32 -> bf16 hi/lo ----------------
__global__ void split_act(const float* __restrict__ X, u16* __restrict__ Xh,
                          u16* __restrict__ Xl, int n4) {
    int i = blockIdx.x * 256 + threadIdx.x;
    if (i < n4) {
        float4 v = *(const float4*)(X + (size_t)i * 4);
        uint32_t h0, l0, h1, l1;
        cvt2(v.x, v.y, h0, l0);
        cvt2(v.z, v.w, h1, l1);
        *(uint2*)(Xh + (size_t)i * 4) = make_uint2(h0, h1);
        *(uint2*)(Xl + (size_t)i * 4) = make_uint2(l0, l1);
    }
}

// ---------------- mma.sync bf16x3 GEMM (pre-split operands) ----------------
// XOR-swizzled SMEM (64B rows, no padding): phys_chunk = c ^ ((row>>1)&3).
// 3-stage cp.async pipeline, ONE __syncthreads per K-tile.
// 128x128 CTA tile, BK=32, 8 warps of 64x32, 2 CTAs/SM.
#define TILE_B  8192                   // 128 rows x 64 B
#define AH_OFF  0
#define AL_OFF  TILE_B
#define BH_OFF  (2 * TILE_B)
#define BL_OFF  (3 * TILE_B)
#define STG_BY  (4 * TILE_B)           // 32768 B per stage
#define GSM_TOTAL (3 * STG_BY)         // 98304 B ; x2 CTAs = 192KB <= 228KB

#define MMA_B(d, a, b0, b1) \
    asm volatile("mma.sync.aligned.m16n8k16.row.col.f32.bf16.bf16.f32 " \
        "{%0,%1,%2,%3}, {%4,%5,%6,%7}, {%8,%9}, {%0,%1,%2,%3};" \
        : "+f"((d)[0]), "+f"((d)[1]), "+f"((d)[2]), "+f"((d)[3]) \
        : "r"((a)[0]), "r"((a)[1]), "r"((a)[2]), "r"((a)[3]), "r"(b0), "r"(b1))

#define LDM_X4(r, addr) \
    asm volatile("ldmatrix.sync.aligned.m8n8.x4.shared.b16 {%0,%1,%2,%3}, [%4];" \
        : "=r"((r)[0]), "=r"((r)[1]), "=r"((r)[2]), "=r"((r)[3]) : "r"(addr))

#define LDM_X2(r0, r1, addr) \
    asm volatile("ldmatrix.sync.aligned.m8n8.x2.shared.b16 {%0,%1}, [%2];" \
        : "=r"(r0), "=r"(r1) : "r"(addr))

__device__ __forceinline__ uint32_t swz(int row, int c) {
    return (uint32_t)((row << 6) + ((c ^ ((row >> 1) & 3)) << 4));
}

__global__ __launch_bounds__(256, 2)
void gemm_bf3(const u16* __restrict__ Ah, const u16* __restrict__ Al, int lda,
              const u16* __restrict__ Bh, const u16* __restrict__ Bl,
              const float* __restrict__ bias,
              float* __restrict__ C, int ldc, int ACC,
              u16* __restrict__ Ch, u16* __restrict__ Cl, int ldhl,
              int M, int K)
{
    extern __shared__ __align__(16) char smem[];
    const uint32_t sb = smem_u32(smem);

    const int tid  = threadIdx.x;
    const int lane = tid & 31;
    const int wid  = tid >> 5;
    const int bm   = blockIdx.y << 7;
    const int bn   = blockIdx.x << 7;
    const int wm   = (wid & 1) << 6;
    const int wn   = (wid >> 1) << 5;
    const int g    = lane >> 2;
    const int tg   = lane & 3;
    const int la15 = lane & 15;
    const int l4   = lane >> 4;
    const int la7  = lane & 7;
    const int l3   = (lane >> 3) & 1;

    float acc[4][4][4];
#pragma unroll
    for (int mi = 0; mi < 4; ++mi)
#pragma unroll
        for (int ni = 0; ni < 4; ++ni)
#pragma unroll
            for (int q = 0; q < 4; ++q) acc[mi][ni][q] = 0.f;

    const int nc = K >> 5;

    // cp.async: thread -> row = tid>>1, chunks {cb, cb+1}
    const int srow = tid >> 1;
    const int cb   = (tid & 1) << 1;
    const int arow = (bm + srow < M) ? (bm + srow) : (M - 1);
    const int aok  = (bm + srow < M) ? 16 : 0;
    const u16* pa_h = Ah + (size_t)arow * lda;
    const u16* pa_l = Al + (size_t)arow * lda;
    const u16* pb_h = Bh + (size_t)(bn + srow) * K;
    const u16* pb_l = Bl + (size_t)(bn + srow) * K;
    const uint32_t sw0 = swz(srow, cb);
    const uint32_t sw1 = swz(srow, cb + 1);

    auto prefetch = [&](int i, int stg_i) {
        const int ke = i << 5;
        const uint32_t base = sb + (uint32_t)stg_i * STG_BY;
#pragma unroll
        for (int j = 0; j < 2; ++j) {
            const uint32_t dst = base + (j ? sw1 : sw0);
            const int eo = ke + ((cb + j) << 3);
            asm volatile("cp.async.cg.shared.global [%0], [%1], 16, %2;"
                         :: "r"(dst + AH_OFF), "l"(pa_h + eo), "r"(aok));
            asm volatile("cp.async.cg.shared.global [%0], [%1], 16, %2;"
                         :: "r"(dst + AL_OFF), "l"(pa_l + eo), "r"(aok));
            asm volatile("cp.async.cg.shared.global [%0], [%1], 16;"
                         :: "r"(dst + BH_OFF), "l"(pb_h + eo));
            asm volatile("cp.async.cg.shared.global [%0], [%1], 16;"
                         :: "r"(dst + BL_OFF), "l"(pb_l + eo));
        }
        asm volatile("cp.async.commit_group;" ::: "memory");
    };

    prefetch(0, 0);
    if (nc > 1) prefetch(1, 1);
    int s = 0;
    for (int i = 0; i < nc; ++i) {
        if (i + 1 < nc) {
            asm volatile("cp.async.wait_group 1;" ::: "memory");
        } else {
            asm volatile("cp.async.wait_group 0;" ::: "memory");
        }
        __syncthreads();
        if (i + 2 < nc) {
            int s2 = s + 2; if (s2 >= 3) s2 -= 3;
            prefetch(i + 2, s2);
        }

        const uint32_t stg = sb + (uint32_t)s * STG_BY;
#pragma unroll
        for (int k16 = 0; k16 < 2; ++k16) {
            uint32_t bh[4][2], bl[4][2];
#pragma unroll
            for (int ni = 0; ni < 4; ++ni) {
                int rb = wn + (ni << 3) + la7;
                uint32_t ab = stg + BH_OFF + swz(rb, (k16 << 1) + l3);
                LDM_X2(bh[ni][0], bh[ni][1], ab);
                LDM_X2(bl[ni][0], bl[ni][1], ab + (BL_OFF - BH_OFF));
            }
#pragma unroll
            for (int mi = 0; mi < 4; ++mi) {
                int ra = wm + (mi << 4) + la15;
                uint32_t aa = stg + AH_OFF + swz(ra, (k16 << 1) + l4);
                uint32_t ah[4], al[4];
                LDM_X4(ah, aa);
                LDM_X4(al, aa + (AL_OFF - AH_OFF));
#pragma unroll
                for (int ni = 0; ni < 4; ++ni) {
                    MMA_B(acc[mi][ni], al, bh[ni][0], bh[ni][1]);
                    MMA_B(acc[mi][ni], ah, bl[ni][0], bl[ni][1]);
                    MMA_B(acc[mi][ni], ah, bh[ni][0], bh[ni][1]);
                }
            }
        }
        if (++s == 3) s = 0;
    }

    // ---- epilogue ----
#pragma unroll
    for (int mi = 0; mi < 4; ++mi) {
#pragma unroll
        for (int ni = 0; ni < 4; ++ni) {
            int c0 = bn + wn + (ni << 3) + (tg << 1);
            float2 bv = *(const float2*)(bias + c0);
#pragma unroll
            for (int half = 0; half < 2; ++half) {
                int r = bm + wm + (mi << 4) + g + (half << 3);
                if (r >= M) continue;
                float ox = acc[mi][ni][half * 2 + 0] + bv.x;
                float oy = acc[mi][ni][half * 2 + 1] + bv.y;
                if (C) {
                    float* p = C + (size_t)r * ldc + c0;
                    if (ACC) { ox += p[0]; oy += p[1]; }
                    p[0] = ox; p[1] = oy;
                }
                if (Ch) {
                    uint32_t hw, lw;
                    cvt2(ox, oy, hw, lw);
                    *(uint32_t*)(Ch + (size_t)r * ldhl + c0) = hw;
                    *(uint32_t*)(Cl + (size_t)r * ldhl + c0) = lw;
                }
            }
        }
    }
}

// ---------------- BatchNorm ----------------
__global__ void colstats_kernel(const float* __restrict__ X, int C, double* __restrict__ sums) {
    int tid  = threadIdx.x;
    int nloc = C >> 8;
    double s[4] = {0, 0, 0, 0}, ss[4] = {0, 0, 0, 0};
    for (int r = blockIdx.x; r < NN; r += gridDim.x) {
        const float* row = X + (size_t)r * C;
        for (int i = 0; i < nloc; ++i) {
            float v = row[i * 256 + tid];
            s[i]  += (double)v;
            ss[i] += (double)v * (double)v;
        }
    }
    for (int i = 0; i < nloc; ++i) {
        atomicAdd(&sums[i * 256 + tid],      s[i]);
        atomicAdd(&sums[C + i * 256 + tid], ss[i]);
    }
}

__global__ void bncoef_kernel(const double* __restrict__ sums,
                              const float* __restrict__ g, const float* __restrict__ b,
                              int C, float* __restrict__ coef) {
    int c = blockIdx.x * blockDim.x + threadIdx.x;
    if (c >= C) return;
    double m  = sums[c] * (1.0 / NN);
    double v  = sums[C + c] * (1.0 / NN) - m * m;
    double sc = (double)g[c] / sqrt(v + 1e-5);
    coef[c]     = (float)sc;
    coef[C + c] = (float)((double)b[c] - m * sc);
}

// BN + LeakyReLU; emits optional f32 and bf16 hi/lo
__global__ void bnact_split(const float* __restrict__ X, int ldx,
                            float* __restrict__ Yf, u16* __restrict__ Yh,
                            u16* __restrict__ Yl, int ldy,
                            int C, const float* __restrict__ coef) {
    int row = blockIdx.x * 4 + threadIdx.y;
    const float* xr = X + (size_t)row * ldx;
    size_t ob = (size_t)row * ldy;
    for (int c = threadIdx.x << 2; c < C; c += 256) {
        float4 v  = *(const float4*)(xr + c);
        float4 sc = *(const float4*)(coef + c);
        float4 sh = *(const float4*)(coef + C + c);
        float4 y;
        y.x = fmaf(v.x, sc.x, sh.x); y.x = (y.x > 0.f) ? y.x : SLOPE * y.x;
        y.y = fmaf(v.y, sc.y, sh.y); y.y = (y.y > 0.f) ? y.y : SLOPE * y.y;
        y.z = fmaf(v.z, sc.z, sh.z); y.z = (y.z > 0.f) ? y.z : SLOPE * y.z;
        y.w = fmaf(v.w, sc.w, sh.w); y.w = (y.w > 0.f) ? y.w : SLOPE * y.w;
        if (Yf) *(float4*)(Yf + ob + c) = y;
        uint32_t h0, l0, h1, l1;
        cvt2(y.x, y.y, h0, l0);
        cvt2(y.z, y.w, h1, l1);
        *(uint2*)(Yh + ob + c) = make_uint2(h0, h1);
        *(uint2*)(Yl + ob + c) = make_uint2(l0, l1);
    }
}

// ---------------- driver ----------------
extern "C" void kernel_launch(void* const* d_in, const int* in_sizes, int n_in,
                              void* d_out, int out_size) {
    const float* x       = (const float*)d_in[0];
    const void*  ei      = d_in[1];
    const float* ew      = (const float*)d_in[2];
    const float* W_emb   = (const float*)d_in[3];
    const float* b_emb   = (const float*)d_in[4];
    const float* conv0_W = (const float*)d_in[5];
    const float* conv0_b = (const float*)d_in[6];
    const float* norm_g  = (const float*)d_in[7];
    const float* norm_b  = (const float*)d_in[8];
    const float* conv_W  = (const float*)d_in[9];
    const float* conv_b  = (const float*)d_in[10];
    const float* mlp_W1  = (const float*)d_in[11];
    const float* mlp_b1  = (const float*)d_in[12];
    const float* mlp_g   = (const float*)d_in[13];
    const float* mlp_bb  = (const float*)d_in[14];
    const float* mlp_W2  = (const float*)d_in[15];
    const float* mlp_b2  = (const float*)d_in[16];
    const float* W_out   = (const float*)d_in[17];
    const float* b_out   = (const float*)d_in[18];
    float* out = (float*)d_out;

    float *P, *h, *zw;
    u16 *Ph, *Pl, *th, *tl, *zh, *zl, *Wh, *Wl;
    int *deg, *fill;
    double* stats;
    float* coef;
    cudaGetSymbolAddress((void**)&P,     g_P);
    cudaGetSymbolAddress((void**)&h,     g_h);
    cudaGetSymbolAddress((void**)&zw,    g_zw);
    cudaGetSymbolAddress((void**)&Ph,    g_Ph);
    cudaGetSymbolAddress((void**)&Pl,    g_Pl);
    cudaGetSymbolAddress((void**)&th,    g_th);
    cudaGetSymbolAddress((void**)&tl,    g_tl);
    cudaGetSymbolAddress((void**)&zh,    g_zh);
    cudaGetSymbolAddress((void**)&zl,    g_zl);
    cudaGetSymbolAddress((void**)&Wh,    g_Wh);
    cudaGetSymbolAddress((void**)&Wl,    g_Wl);
    cudaGetSymbolAddress((void**)&deg,   g_deg);
    cudaGetSymbolAddress((void**)&fill,  g_fill);
    cudaGetSymbolAddress((void**)&stats, g_stats);
    cudaGetSymbolAddress((void**)&coef,  g_coef);

    cudaFuncSetAttribute(gemm_bf3, cudaFuncAttributeMaxDynamicSharedMemorySize, GSM_TOTAL);

    const int MT = (NN + 127) / 128;   // 391 M-tiles
    dim3 blk256(256);
    dim3 spmm_blk(64, 4);
    dim3 spmm_grd(NN / 4);
    dim3 bn_blk(64, 4);
    dim3 bn_grd(NN / 4);
    dim3 tb(32, 8);

    // ---- launch order: gemm_bf3 at index 3 so fixed-index ncu capture hits it ----
    transpose_split<<<dim3(HH / 32, CIN / 32), tb>>>(W_emb, Wh + OFF_EMB, Wl + OFF_EMB, CIN, HH);  // 0
    split_act<<<(NN * CIN / 4 + 255) / 256, blk256>>>(x, zh, zl, NN * CIN / 4);                    // 1
    detect_kernel<<<1, 256>>>((const unsigned*)ei);                                                // 2
    gemm_bf3<<<dim3(HH / 128, MT), blk256, GSM_TOTAL>>>(                                           // 3
        zh, zl, CIN, Wh + OFF_EMB, Wl + OFF_EMB, b_emb,
        P, P_LD, 0, Ph, Pl, P_LD, NN, CIN);

    // ---- CSR build ----
    zero_words<<<(NN + 255) / 256, blk256>>>((unsigned*)deg, NN);
    zero_words<<<(NN + 255) / 256, blk256>>>((unsigned*)fill, NN);
    hist_kernel<<<EE / 256, blk256>>>(ei);
    exscan_kernel<<<1, 1024>>>();
    scatter_kernel<<<EE / 256, blk256>>>(ei, ew);

    // ---- remaining weight transposes ----
    transpose_split<<<dim3(HH / 32, P_LD / 32), tb>>>(conv0_W, Wh + OFF_C0, Wl + OFF_C0, P_LD, HH);
    for (int l = 0; l < 3; ++l) {
        transpose_split<<<dim3(HH / 32, P_LD / 32), tb>>>(
            conv_W + (size_t)l * P_LD * HH, Wh + OFF_CV + (size_t)l * P_LD * HH,
            Wl + OFF_CV + (size_t)l * P_LD * HH, P_LD, HH);
        transpose_split<<<dim3(H4 / 32, HH / 32), tb>>>(
            mlp_W1 + (size_t)l * HH * H4, Wh + OFF_W1 + (size_t)l * HH * H4,
            Wl + OFF_W1 + (size_t)l * HH * H4, HH, H4);
        transpose_split<<<dim3(HH / 32, H4 / 32), tb>>>(
            mlp_W2 + (size_t)l * H4 * HH, Wh + OFF_W2 + (size_t)l * H4 * HH,
            Wl + OFF_W2 + (size_t)l * H4 * HH, H4, HH);
    }
    transpose_split<<<dim3(CIN / 32, HH / 32), tb>>>(W_out, Wh + OFF_OUT, Wl + OFF_OUT, HH, CIN);

    // ---- hops + conv0 ----
    spmm_kernel<<<spmm_grd, spmm_blk>>>(P, P + HH, Ph + HH, Pl + HH);
    spmm_kernel<<<spmm_grd, spmm_blk>>>(P + HH, nullptr, Ph + 2 * HH, Pl + 2 * HH);
    gemm_bf3<<<dim3(HH / 128, MT), blk256, GSM_TOTAL>>>(
        Ph, Pl, P_LD, Wh + OFF_C0, Wl + OFF_C0, conv0_b,
        h, HH, 0, nullptr, nullptr, 0, NN, P_LD);

    for (int l = 0; l < 3; ++l) {
        zero_words<<<16, blk256>>>((unsigned*)stats, 4096);
        colstats_kernel<<<512, blk256>>>(h, HH, stats);
        bncoef_kernel<<<1, 256>>>(stats, norm_g + l * HH, norm_b + l * HH, HH, coef);
        bnact_split<<<bn_grd, bn_blk>>>(h, HH, P, Ph, Pl, P_LD, HH, coef);
        spmm_kernel<<<spmm_grd, spmm_blk>>>(P, P + HH, Ph + HH, Pl + HH);
        spmm_kernel<<<spmm_grd, spmm_blk>>>(P + HH, nullptr, Ph + 2 * HH, Pl + 2 * HH);
        gemm_bf3<<<dim3(HH / 128, MT), blk256, GSM_TOTAL>>>(
            Ph, Pl, P_LD, Wh + OFF_CV + (size_t)l * P_LD * HH,
            Wl + OFF_CV + (size_t)l * P_LD * HH, conv_b + l * HH,
            nullptr, 0, 0, th, tl, HH, NN, P_LD);
        gemm_bf3<<<dim3(H4 / 128, MT), blk256, GSM_TOTAL>>>(
            th, tl, HH, Wh + OFF_W1 + (size_t)l * HH * H4,
            Wl + OFF_W1 + (size_t)l * HH * H4, mlp_b1 + l * H4,
            zw, H4, 0, nullptr, nullptr, 0, NN, HH);
        zero_words<<<16, blk256>>>((unsigned*)stats, 4096);
        colstats_kernel<<<512, blk256>>>(zw, H4, stats);
        bncoef_kernel<<<4, 256>>>(stats, mlp_g + l * H4, mlp_bb + l * H4, H4, coef);
        bnact_split<<<bn_grd, bn_blk>>>(zw, H4, nullptr, zh, zl, H4, H4, coef);
        gemm_bf3<<<dim3(HH / 128, MT), blk256, GSM_TOTAL>>>(
            zh, zl, H4, Wh + OFF_W2 + (size_t)l * H4 * HH,
            Wl + OFF_W2 + (size_t)l * H4 * HH, mlp_b2 + l * HH,
            h, HH, 1, nullptr, nullptr, 0, NN, H4);
    }

    // ---- out = h @ W_out + b_out ----
    split_act<<<(NN * HH / 4 + 255) / 256, blk256>>>(h, th, tl, NN * HH / 4);
    gemm_bf3<<<dim3(CIN / 128, MT), blk256, GSM_TOTAL>>>(
        th, tl, HH, Wh + OFF_OUT, Wl + OFF_OUT, b_out,
        out, CIN, 0, nullptr, nullptr, 0, NN, HH);
}